// round 14
// baseline (speedup 1.0000x reference)
#include <cuda_runtime.h>
#include <cuda_bf16.h>
#include <math.h>
#include <stdint.h>

// Problem constants
#define S_   1024
#define CA_  768
#define CS_  384
#define CZ_  64
#define H_   16
#define CH_  48     // head dim
#define C3_  144    // 3*CH
#define S2_  (S_ * S_)

// ---------------------------------------------------------------------------
// Static scratch (device globals — no cudaMalloc allowed)
// ---------------------------------------------------------------------------
__device__ float g_an[S_ * CA_];           // LN(a) per layer (fp32 aux)
__device__ float g_aout[S_ * CA_];         // gated attention output
__device__ float g_anew[S_ * CA_];         // a after layer 0
__device__ float g_wbias[32];
__device__ float g_sg[S_ * 3072];          // [og l0 | tg l0 | og l1 | tg l1]
__device__ float g_adab[3072];             // stacked adaLN biases (2 layers)
__device__ float g_sgb[3072];              // stacked sgate biases

__device__ __align__(16) __nv_bfloat16 g_bb0[H_ * S2_];   // layer-0 bias [h][i][j]
__device__ __align__(16) __nv_bfloat16 g_bb1[H_ * S2_];   // layer-1 bias
__device__ __align__(16) __nv_bfloat16 g_wbf[16908288];   // all weights + s, bf16
__device__ __align__(16) __nv_bfloat16 g_shatb[S_ * CS_];
__device__ __align__(16) __nv_bfloat16 g_a23b[S_ * 1536]; // a2 | a3
__device__ __align__(16) __nv_bfloat16 g_qb[S_ * CA_];
__device__ __align__(16) __nv_bfloat16 g_kvgb[S_ * 3 * CA_];
__device__ __align__(16) __nv_bfloat16 g_obb[S_ * CA_];
__device__ __align__(16) __nv_bfloat16 g_bbb[S_ * 2 * CA_];
__device__ __align__(16) __nv_bfloat16 g_vtb[H_ * CH_ * S_];  // Vt (plain transpose)
__device__ __align__(16) __nv_bfloat16 g_wpbf[32 * 64];   // folded z-proj weights

// ---------------------------------------------------------------------------
// Helpers
// ---------------------------------------------------------------------------
__device__ __forceinline__ float sigf(float x) { return 1.0f / (1.0f + expf(-x)); }

__device__ __forceinline__ void mma_bf16(float* d, const uint32_t* a,
                                         uint32_t b0, uint32_t b1) {
    asm volatile(
        "mma.sync.aligned.m16n8k16.row.col.f32.bf16.bf16.f32 "
        "{%0,%1,%2,%3}, {%4,%5,%6,%7}, {%8,%9}, {%0,%1,%2,%3};"
        : "+f"(d[0]), "+f"(d[1]), "+f"(d[2]), "+f"(d[3])
        : "r"(a[0]), "r"(a[1]), "r"(a[2]), "r"(a[3]), "r"(b0), "r"(b1));
}

__device__ __forceinline__ void cp16(uint32_t smem, const void* g, int sbytes) {
    asm volatile("cp.async.cg.shared.global [%0], [%1], 16, %2;\n"
                 :: "r"(smem), "l"(g), "r"(sbytes));
}
#define CP_COMMIT() asm volatile("cp.async.commit_group;\n" ::)

__device__ __forceinline__ float toF(float v) { return v; }
__device__ __forceinline__ float toF(__nv_bfloat16 v) { return __bfloat162float(v); }
__device__ __forceinline__ void storeOut(float v, float* p) { *p = v; }
__device__ __forceinline__ void storeOut(float v, __nv_bfloat16* p) { *p = __float2bfloat16_rn(v); }

// ---------------------------------------------------------------------------
// Weight/act conversion fp32 -> bf16 (optionally scaling columns by scl[c])
// ---------------------------------------------------------------------------
struct CvtArgs {
    const float* src[24];
    const float* scl[24];
    __nv_bfloat16* dst[24];
    int len[24];
    int smod;
    int nseg;
};

__global__ void __launch_bounds__(256) cvt_kernel(CvtArgs a) {
    int s = blockIdx.y;
    if (s >= a.nseg) return;
    const float* src = a.src[s];
    const float* scl = a.scl[s];
    __nv_bfloat16* dst = a.dst[s];
    int n = a.len[s];
    for (long long i = (long long)(blockIdx.x * 256 + threadIdx.x) * 2; i < n;
         i += (long long)gridDim.x * 512) {
        float2 v = *(const float2*)&src[i];
        if (scl) { int c = (int)(i % a.smod); v.x *= scl[c]; v.y *= scl[c + 1]; }
        *(__nv_bfloat162*)&dst[i] = __floats2bfloat162_rn(v.x, v.y);
    }
}

// ---------------------------------------------------------------------------
// Stacked bias prep
// ---------------------------------------------------------------------------
__global__ void bias_prep(const float* __restrict__ apb_b, const float* __restrict__ trpb_b,
                          const float* __restrict__ out_b, const float* __restrict__ tr_s_b,
                          float* __restrict__ adab, float* __restrict__ sgb) {
    int i = blockIdx.x * 256 + threadIdx.x;
    if (i < 3072) {
        int l = i / 1536, n = i % 1536;
        adab[i] = (n < CA_) ? apb_b[l * CA_ + n] : trpb_b[l * CA_ + n - CA_];
    } else if (i < 6144) {
        int j = i - 3072;
        int l = j / 1536, n = j % 1536;
        sgb[j] = (n < CA_) ? out_b[l * CA_ + n] : tr_s_b[l * CA_ + n - CA_];
    }
}

// ---------------------------------------------------------------------------
// LayerNorm (no affine): one WARP per row, 8 rows/block. W % 128 == 0, W<=768.
// ---------------------------------------------------------------------------
template <typename OutT>
__global__ void __launch_bounds__(256) ln_kernel(const float* __restrict__ x,
                                                 OutT* __restrict__ y, int W) {
    int warp = threadIdx.x >> 5, lane = threadIdx.x & 31;
    long long row = (long long)blockIdx.x * 8 + warp;
    const float4* xr = (const float4*)(x + row * W);
    int npl = W >> 7;
    float4 v[6];
    float s = 0.f;
    #pragma unroll 6
    for (int i = 0; i < npl; i++) {
        v[i] = xr[lane + i * 32];
        s += v[i].x + v[i].y + v[i].z + v[i].w;
    }
    #pragma unroll
    for (int o = 16; o; o >>= 1) s += __shfl_xor_sync(0xffffffffu, s, o);
    float mean = s / (float)W;
    float vs = 0.f;
    #pragma unroll 6
    for (int i = 0; i < npl; i++) {
        float a = v[i].x - mean, b = v[i].y - mean, c = v[i].z - mean, d = v[i].w - mean;
        vs += a * a + b * b + c * c + d * d;
    }
    #pragma unroll
    for (int o = 16; o; o >>= 1) vs += __shfl_xor_sync(0xffffffffu, vs, o);
    float rstd = rsqrtf(vs / (float)W + 1e-5f);
    #pragma unroll 6
    for (int i = 0; i < npl; i++) {
        float a = (v[i].x - mean) * rstd, b = (v[i].y - mean) * rstd;
        float c = (v[i].z - mean) * rstd, d = (v[i].w - mean) * rstd;
        if constexpr (sizeof(OutT) == 4) {
            ((float4*)(y + row * W))[lane + i * 32] = make_float4(a, b, c, d);
        } else {
            uint2 u;
            __nv_bfloat162 p0 = __floats2bfloat162_rn(a, b);
            __nv_bfloat162 p1 = __floats2bfloat162_rn(c, d);
            memcpy(&u.x, &p0, 4);
            memcpy(&u.y, &p1, 4);
            ((uint2*)(y + row * W))[lane + i * 32] = u;
        }
    }
}

// ---------------------------------------------------------------------------
// z projection prep
// ---------------------------------------------------------------------------
__global__ void zprep_kernel(const float* __restrict__ pw, const float* __restrict__ pb,
                             const float* __restrict__ bw, const float* __restrict__ bb,
                             __nv_bfloat16* __restrict__ Wp, float* __restrict__ Wbias) {
    int lh = threadIdx.x;
    if (lh >= 32) return;
    int l = lh >> 4;
    float bs = 0.f;
    for (int c = 0; c < 64; c++) {
        float w = bw[lh * 64 + c];
        Wp[lh * 64 + c] = __float2bfloat16_rn(pw[l * 64 + c] * w);
        bs += pb[l * 64 + c] * w;
    }
    Wbias[lh] = bs + bb[lh];
}

// ---------------------------------------------------------------------------
// z projection: coalesced load -> bf16 smem -> vectorized per-row LN ->
// mma (128x32x64) -> bf16 bias output [h][i*S+j] with coalesced stores.
// ---------------------------------------------------------------------------
__global__ void __launch_bounds__(256) zproj_kernel(const float* __restrict__ z,
                                                    const __nv_bfloat16* __restrict__ Wp,
                                                    const float* __restrict__ Wbias,
                                                    __nv_bfloat16* __restrict__ b0,
                                                    __nv_bfloat16* __restrict__ b1) {
    __shared__ __nv_bfloat16 zb[128][72];
    __shared__ __nv_bfloat16 wsm[32][72];
    __shared__ __nv_bfloat16 sOut[32][136];
    __shared__ float bsm[32];
    int tid = threadIdx.x;
    long long base = (long long)blockIdx.x * 8192;

    #pragma unroll
    for (int i = 0; i < 8; i++) {
        int idx = tid + i * 256;
        float4 t = *(const float4*)&z[base + (long long)idx * 4];
        int r = idx >> 4, c = (idx & 15) * 4;
        *(__nv_bfloat162*)&zb[r][c]     = __floats2bfloat162_rn(t.x, t.y);
        *(__nv_bfloat162*)&zb[r][c + 2] = __floats2bfloat162_rn(t.z, t.w);
    }
    #pragma unroll
    for (int i = 0; i < 8; i++) {
        int idx = tid + i * 256;
        wsm[idx >> 6][idx & 63] = Wp[idx];
    }
    if (tid < 32) bsm[tid] = Wbias[tid];
    __syncthreads();

    {
        int row = tid >> 1, half = tid & 1;
        uint4* zr = (uint4*)&zb[row][half * 32];
        uint4 u[4];
        float vv[32];
        float s = 0.f, s2 = 0.f;
        #pragma unroll
        for (int i = 0; i < 4; i++) {
            u[i] = zr[i];
            const __nv_bfloat162* p = (const __nv_bfloat162*)&u[i];
            #pragma unroll
            for (int w = 0; w < 4; w++) {
                float2 f = __bfloat1622float2(p[w]);
                vv[i * 8 + w * 2] = f.x; vv[i * 8 + w * 2 + 1] = f.y;
                s += f.x + f.y; s2 += f.x * f.x + f.y * f.y;
            }
        }
        s  += __shfl_xor_sync(0xffffffffu, s, 1);
        s2 += __shfl_xor_sync(0xffffffffu, s2, 1);
        float m = s * (1.f / 64.f);
        float rs = rsqrtf(s2 * (1.f / 64.f) - m * m + 1e-5f);
        #pragma unroll
        for (int i = 0; i < 4; i++) {
            __nv_bfloat162* p = (__nv_bfloat162*)&u[i];
            #pragma unroll
            for (int w = 0; w < 4; w++)
                p[w] = __floats2bfloat162_rn((vv[i * 8 + w * 2] - m) * rs,
                                             (vv[i * 8 + w * 2 + 1] - m) * rs);
            zr[i] = u[i];
        }
    }
    __syncthreads();

    int w = tid >> 5, lane = tid & 31, qr = lane >> 2, qc = lane & 3;
    float acc[4][4] = {};
    const uint32_t* zw = (const uint32_t*)&zb[0][0];
    const uint32_t* ww = (const uint32_t*)&wsm[0][0];
    #pragma unroll
    for (int kc = 0; kc < 4; kc++) {
        uint32_t af[4];
        int r = w * 16 + qr;
        af[0] = zw[r * 36 + kc * 8 + qc];
        af[1] = zw[(r + 8) * 36 + kc * 8 + qc];
        af[2] = zw[r * 36 + kc * 8 + 4 + qc];
        af[3] = zw[(r + 8) * 36 + kc * 8 + 4 + qc];
        #pragma unroll
        for (int j = 0; j < 4; j++) {
            int n = j * 8 + qr;
            mma_bf16(acc[j], af, ww[n * 36 + kc * 8 + qc], ww[n * 36 + kc * 8 + 4 + qc]);
        }
    }
    #pragma unroll
    for (int j = 0; j < 4; j++) {
        #pragma unroll
        for (int e = 0; e < 4; e++) {
            int mm = w * 16 + qr + ((e >= 2) ? 8 : 0);
            int n = j * 8 + 2 * qc + (e & 1);
            sOut[n][mm] = __float2bfloat16_rn(acc[j][e] + bsm[n]);
        }
    }
    __syncthreads();
    long long rg0 = (long long)blockIdx.x * 128;
    #pragma unroll
    for (int it = 0; it < 2; it++) {
        int lh = tid >> 3, part = (tid & 7) + it * 8;
        uint4 v = *(const uint4*)&sOut[lh][part * 8];
        __nv_bfloat16* dst = ((lh < 16) ? b0 : b1) +
                             (long long)(lh & 15) * S2_ + rg0 + part * 8;
        *(uint4*)dst = v;
    }
}

// ---------------------------------------------------------------------------
// Vt[h][c][r] = v[h][r][c]  (plain transpose, bf16)
// ---------------------------------------------------------------------------
__global__ void __launch_bounds__(256) vt_kernel(const __nv_bfloat16* __restrict__ kvg,
                                                 __nv_bfloat16* __restrict__ vt) {
    __shared__ __nv_bfloat16 sv[48][136];
    int h = blockIdx.y, bm = blockIdx.x * 128, tid = threadIdx.x;
    const __nv_bfloat16* vbase = kvg + (long long)h * S_ * C3_ + CH_;
    for (int id = tid; id < 128 * 24; id += 256) {
        int r = id / 24, c2 = id % 24;
        __nv_bfloat162 v = *(const __nv_bfloat162*)&vbase[(long long)(bm + r) * C3_ + 2 * c2];
        sv[2 * c2][r]     = v.x;
        sv[2 * c2 + 1][r] = v.y;
    }
    __syncthreads();
    for (int id = tid; id < 48 * 16; id += 256) {
        int c = id >> 4, chunk = id & 15;
        *(uint4*)&vt[(long long)h * CH_ * S_ + (long long)c * S_ + bm + chunk * 8] =
            *(const uint4*)&sv[c][chunk * 8];
    }
}

// ---------------------------------------------------------------------------
// Fused flash attention: per block = (head, 128 t-rows), loop over 8 r-tiles.
// o[t,c] = sigmoid(g[t,c]) * (sum_r exp(q·k/48+bias[r,t]) V[r,c]) / rowsum[t]
// P never hits memory. No max-subtraction (scores bounded; validated R6+).
// Dynamic smem 138752 B.
// ---------------------------------------------------------------------------
__global__ void __launch_bounds__(256) attn_fused_kernel(
    const __nv_bfloat16* __restrict__ kvg,   // [H][S][144]
    const __nv_bfloat16* __restrict__ q,     // [H][S][48]
    const __nv_bfloat16* __restrict__ vt,    // [H][48][S]
    const __nv_bfloat16* __restrict__ bias,  // [H][r][t]
    __nv_bfloat16* __restrict__ obb) {       // [H][S][48]
    const int h = blockIdx.y;
    const int bt = blockIdx.x * 128;
    const int tid = threadIdx.x, lane = tid & 31, w = tid >> 5;
    const int qr = lane >> 2, qc = lane & 3;

    extern __shared__ char smraw[];
    __nv_bfloat16* Qs = (__nv_bfloat16*)smraw;          // [128][56]
    __nv_bfloat16* Ks = Qs + 128 * 56;                  // [2][128][56]
    __nv_bfloat16* Vs = Ks + 2 * 128 * 56;              // [2][48][136]
    __nv_bfloat16* Bs = Vs + 2 * 48 * 136;              // [2][128][136]

    const __nv_bfloat16* qbase = q + (long long)h * S_ * CH_;
    const __nv_bfloat16* kbase = kvg + (long long)h * S_ * C3_;
    const __nv_bfloat16* vbase = vt + (long long)h * CH_ * S_;
    const __nv_bfloat16* bbase = bias + (long long)h * S2_;

    // Q tile (sync load, once, full 48 elements per row)
    for (int id = tid; id < 128 * 24; id += 256) {
        int r = id / 24, c2 = id % 24;
        *(__nv_bfloat162*)&Qs[r * 56 + 2 * c2] =
            *(const __nv_bfloat162*)&qbase[(long long)(bt + r) * CH_ + 2 * c2];
    }

    uint32_t kS = (uint32_t)__cvta_generic_to_shared(Ks);
    uint32_t vS = (uint32_t)__cvta_generic_to_shared(Vs);
    uint32_t bS = (uint32_t)__cvta_generic_to_shared(Bs);

    auto issue = [&](int st, int rt) {
        int r0 = rt * 128;
        // bias tile: 128 rows x 16 segs (full)
        #pragma unroll
        for (int i = 0; i < 8; i++) {
            int id = tid + i * 256;
            int r = id >> 4, seg = id & 15;
            cp16(bS + st * 128 * 272 + r * 272 + seg * 16,
                 bbase + (long long)(r0 + r) * S_ + bt + seg * 8, 16);
        }
        // K tile: 128 rows x 6 segs of 8 bf16 = full 48 elements
        #pragma unroll
        for (int i = 0; i < 3; i++) {
            int id = tid + i * 256;          // 768 = 128*6
            int r = id / 6, seg = id % 6;
            cp16(kS + st * 128 * 112 + r * 112 + seg * 16,
                 kbase + (long long)(r0 + r) * C3_ + seg * 8, 16);
        }
        // V tile: 48 rows x 16 segs of 8 bf16 = full 128 elements
        #pragma unroll
        for (int i = 0; i < 3; i++) {
            int id = tid + i * 256;          // 768 = 48*16
            int c = id >> 4, seg = id & 15;
            cp16(vS + st * 48 * 272 + c * 272 + seg * 16,
                 vbase + (long long)c * S_ + r0 + seg * 8, 16);
        }
    };

    issue(0, 0);
    CP_COMMIT();
    __syncthreads();   // Q tile visible to all

    // Q fragments (fixed across the whole kernel)
    uint32_t qa[3][4];
    {
        const uint32_t* q0 = (const uint32_t*)&Qs[(w * 16 + qr) * 56];
        const uint32_t* q8 = (const uint32_t*)&Qs[(w * 16 + qr + 8) * 56];
        #pragma unroll
        for (int ks = 0; ks < 3; ks++) {
            qa[ks][0] = q0[ks * 8 + qc];
            qa[ks][1] = q8[ks * 8 + qc];
            qa[ks][2] = q0[ks * 8 + 4 + qc];
            qa[ks][3] = q8[ks * 8 + 4 + qc];
        }
    }

    float oacc[6][4] = {};
    float rsum0 = 0.f, rsum1 = 0.f;
    const float inv48 = 1.f / 48.f;
    const int t0 = w * 16 + qr;

    for (int rt = 0; rt < 8; rt++) {
        asm volatile("cp.async.wait_group 0;\n" ::);
        __syncthreads();
        if (rt + 1 < 8) issue((rt + 1) & 1, rt + 1);
        CP_COMMIT();
        int st = rt & 1;

        // S = Q·K^T  (per warp: 16 t x 128 r)
        float sacc[16][4];
        #pragma unroll
        for (int j = 0; j < 16; j++) {
            sacc[j][0] = sacc[j][1] = sacc[j][2] = sacc[j][3] = 0.f;
        }
        #pragma unroll
        for (int ks = 0; ks < 3; ks++) {
            #pragma unroll
            for (int j = 0; j < 16; j++) {
                const uint32_t* kr = (const uint32_t*)&Ks[st * 128 * 56 + (j * 8 + qr) * 56];
                mma_bf16(sacc[j], qa[ks], kr[ks * 8 + qc], kr[ks * 8 + 4 + qc]);
            }
        }

        // P = exp(S/48 + bias) -> A-frags (C-frag == A-frag identity); o += P·V
        const __nv_bfloat16* bst = &Bs[st * 128 * 136];
        #pragma unroll
        for (int kt = 0; kt < 8; kt++) {
            uint32_t af[4];
            #pragma unroll
            for (int jj = 0; jj < 2; jj++) {
                int j = kt * 2 + jj;
                int r0l = j * 8 + 2 * qc;
                float b00 = toF(bst[r0l * 136 + t0]);
                float b10 = toF(bst[(r0l + 1) * 136 + t0]);
                float b01 = toF(bst[r0l * 136 + t0 + 8]);
                float b11 = toF(bst[(r0l + 1) * 136 + t0 + 8]);
                float e0 = __expf(sacc[j][0] * inv48 + b00);
                float e1 = __expf(sacc[j][1] * inv48 + b10);
                float e2 = __expf(sacc[j][2] * inv48 + b01);
                float e3 = __expf(sacc[j][3] * inv48 + b11);
                rsum0 += e0 + e1;
                rsum1 += e2 + e3;
                __nv_bfloat162 p01 = __floats2bfloat162_rn(e0, e1);
                __nv_bfloat162 p23 = __floats2bfloat162_rn(e2, e3);
                memcpy(&af[jj * 2],     &p01, 4);
                memcpy(&af[jj * 2 + 1], &p23, 4);
            }
            #pragma unroll
            for (int ct = 0; ct < 6; ct++) {
                const uint32_t* vr = (const uint32_t*)&Vs[st * 48 * 136 + (ct * 8 + qr) * 136];
                mma_bf16(oacc[ct], af, vr[kt * 8 + qc], vr[kt * 8 + 4 + qc]);
            }
        }
    }

    // reduce row sums across the quad (qc lanes share a t-row)
    rsum0 += __shfl_xor_sync(0xffffffffu, rsum0, 1);
    rsum0 += __shfl_xor_sync(0xffffffffu, rsum0, 2);
    rsum1 += __shfl_xor_sync(0xffffffffu, rsum1, 1);
    rsum1 += __shfl_xor_sync(0xffffffffu, rsum1, 2);
    float inv0 = 1.f / rsum0, inv1 = 1.f / rsum1;

    const __nv_bfloat16* gbase = kvg + (long long)h * S_ * C3_ + 2 * CH_;
    __nv_bfloat16* obase = obb + (long long)h * S_ * CH_;
    #pragma unroll
    for (int ct = 0; ct < 6; ct++) {
        int c = ct * 8 + 2 * qc;
        __nv_bfloat162 g0 = *(const __nv_bfloat162*)&gbase[(long long)(bt + t0) * C3_ + c];
        __nv_bfloat162 g1 = *(const __nv_bfloat162*)&gbase[(long long)(bt + t0 + 8) * C3_ + c];
        float o0 = oacc[ct][0] * inv0 * sigf(toF(g0.x));
        float o1 = oacc[ct][1] * inv0 * sigf(toF(g0.y));
        float o2 = oacc[ct][2] * inv1 * sigf(toF(g1.x));
        float o3 = oacc[ct][3] * inv1 * sigf(toF(g1.y));
        *(__nv_bfloat162*)&obase[(long long)(bt + t0) * CH_ + c] =
            __floats2bfloat162_rn(o0, o1);
        *(__nv_bfloat162*)&obase[(long long)(bt + t0 + 8) * CH_ + c] =
            __floats2bfloat162_rn(o2, o3);
    }
}

// ---------------------------------------------------------------------------
// Tensor-core bf16 GEMM (NT):  C[m,n] = sum_k A[m,k] * B[n,k]
// cp.async multi-stage ring, one sync per k-chunk.
// Block tile 128x64, BK=32, 256 threads (8 warps, 4x2), warp tile 32x32.
// ---------------------------------------------------------------------------
enum { EPI_PLAIN = 0, EPI_ADALN = 5, EPI_GLU = 6,
       EPI_SPLIT = 7, EPI_SGATE = 8, EPI_MULT = 9, EPI_TRF2 = 10 };

template <int EPI, bool DUAL, typename OutT, typename AuxT>
__global__ void __launch_bounds__(256) gemm_tc(
    const __nv_bfloat16* __restrict__ A, const __nv_bfloat16* __restrict__ B1,
    const __nv_bfloat16* __restrict__ B2, const float* __restrict__ bias,
    const AuxT* __restrict__ aux, const float* __restrict__ aux2,
    OutT* __restrict__ Cp, OutT* __restrict__ Cp2,
    int M, int N, int K, int lda, int ldb, int ldc, int ldc2, int nsplit, int aux_ld,
    long long sA, long long sB, long long sC, long long sAux) {
    constexpr int NST = DUAL ? 2 : 3;
    const int tid = threadIdx.x;
    const int lane = tid & 31, warp = tid >> 5;
    const int wm = warp >> 1, wn = warp & 1;
    const int bm = blockIdx.y * 128, bn = blockIdx.x * 64;
    const int bz = blockIdx.z;
    A += bz * sA;
    B1 += bz * sB;
    if constexpr (DUAL) B2 += bz * sB;
    Cp += bz * sC;
    if (aux) aux += bz * sAux;

    __shared__ __nv_bfloat16 As[NST][128][40];
    __shared__ __nv_bfloat16 Bs1[NST][64][40];
    __shared__ __nv_bfloat16 Bs2[DUAL ? NST : 1][64][40];

    float acc1[2][4][4] = {};
    float acc2[2][4][4] = {};
    const int qr = lane >> 2, qc = lane & 3;
    const int nk = (K + 31) / 32;

    auto do_mma = [&](int st) {
        #pragma unroll
        for (int ks = 0; ks < 2; ks++) {
            uint32_t af[2][4];
            #pragma unroll
            for (int i = 0; i < 2; i++) {
                int r = wm * 32 + i * 16 + qr;
                const uint32_t* arow  = (const uint32_t*)&As[st][r][0];
                const uint32_t* arow8 = (const uint32_t*)&As[st][r + 8][0];
                af[i][0] = arow[ks * 8 + qc];
                af[i][1] = arow8[ks * 8 + qc];
                af[i][2] = arow[ks * 8 + 4 + qc];
                af[i][3] = arow8[ks * 8 + 4 + qc];
            }
            #pragma unroll
            for (int j = 0; j < 4; j++) {
                int n = wn * 32 + j * 8 + qr;
                const uint32_t* brow = (const uint32_t*)&Bs1[st][n][0];
                uint32_t b0 = brow[ks * 8 + qc];
                uint32_t b1 = brow[ks * 8 + 4 + qc];
                #pragma unroll
                for (int i = 0; i < 2; i++) mma_bf16(acc1[i][j], af[i], b0, b1);
                if constexpr (DUAL) {
                    const uint32_t* brow2 = (const uint32_t*)&Bs2[st][n][0];
                    uint32_t c0 = brow2[ks * 8 + qc];
                    uint32_t c1 = brow2[ks * 8 + 4 + qc];
                    #pragma unroll
                    for (int i = 0; i < 2; i++) mma_bf16(acc2[i][j], af[i], c0, c1);
                }
            }
        }
    };

    uint32_t aBase = (uint32_t)__cvta_generic_to_shared(&As[0][0][0]);
    uint32_t bBase = (uint32_t)__cvta_generic_to_shared(&Bs1[0][0][0]);
    uint32_t b2Base = 0;
    if constexpr (DUAL) b2Base = (uint32_t)__cvta_generic_to_shared(&Bs2[0][0][0]);

    auto issue = [&](int st, int k0) {
        #pragma unroll
        for (int i = 0; i < 2; i++) {
            int id = tid + i * 256;
            int r = id >> 2, cp4 = id & 3;
            int kk = k0 + cp4 * 8;
            const __nv_bfloat16* src = A + (long long)(bm + r) * lda + kk;
            int sb = (kk < K) ? 16 : 0;
            if (!sb) src = A;
            cp16(aBase + st * 128 * 80 + r * 80 + cp4 * 16, src, sb);
        }
        {
            int r = tid >> 2, cp4 = tid & 3;
            int kk = k0 + cp4 * 8;
            int sb = (kk < K) ? 16 : 0;
            const __nv_bfloat16* src = B1 + (long long)(bn + r) * ldb + kk;
            if (!sb) src = B1;
            cp16(bBase + st * 64 * 80 + r * 80 + cp4 * 16, src, sb);
            if constexpr (DUAL) {
                const __nv_bfloat16* src2 = B2 + (long long)(bn + r) * ldb + kk;
                if (!sb) src2 = B2;
                cp16(b2Base + st * 64 * 80 + r * 80 + cp4 * 16, src2, sb);
            }
        }
    };

    #pragma unroll
    for (int p = 0; p < NST - 1; p++) {
        if (p < nk) issue(p, p * 32);
        CP_COMMIT();
    }
    for (int ic = 0; ic < nk; ic++) {
        if constexpr (NST == 3) asm volatile("cp.async.wait_group 1;\n" ::);
        else                    asm volatile("cp.async.wait_group 0;\n" ::);
        __syncthreads();
        int pn = ic + NST - 1;
        if (pn < nk) issue(pn % NST, pn * 32);
        CP_COMMIT();
        do_mma(ic % NST);
    }

    // ---- epilogue ----
    #pragma unroll
    for (int i = 0; i < 2; i++) {
        #pragma unroll
        for (int j = 0; j < 4; j++) {
            int m0 = bm + wm * 32 + i * 16 + qr;
            int n0 = bn + wn * 32 + j * 8 + 2 * qc;
            #pragma unroll
            for (int e = 0; e < 4; e++) {
                int m = m0 + ((e >= 2) ? 8 : 0);
                int n = n0 + (e & 1);
                if (n >= N) continue;
                float v = acc1[i][j][e];
                if constexpr (EPI == EPI_PLAIN) {
                    storeOut(v + (bias ? bias[n] : 0.f), &Cp[(long long)m * ldc + n]);
                } else if constexpr (EPI == EPI_ADALN) {
                    int na = (n >= CA_) ? n - CA_ : n;
                    storeOut(sigf((v + bias[n]) * toF(aux[(long long)m * aux_ld + na]) +
                                  acc2[i][j][e]),
                             &Cp[(long long)m * ldc + n]);
                } else if constexpr (EPI == EPI_GLU) {
                    storeOut(v * sigf(v) * acc2[i][j][e], &Cp[(long long)m * ldc + n]);
                } else if constexpr (EPI == EPI_SPLIT) {
                    float out = v + ((n < nsplit) ? bias[n] : 0.f);
                    if (n < nsplit) storeOut(out, &Cp[(long long)m * ldc + n]);
                    else            storeOut(out, &Cp2[(long long)m * ldc2 + (n - nsplit)]);
                } else if constexpr (EPI == EPI_SGATE) {
                    bool sg = (((bn / 768) & 1) == 0);
                    float out = v + bias[n];
                    storeOut(sg ? sigf(out) : out, &Cp[(long long)m * ldc + n]);
                } else if constexpr (EPI == EPI_MULT) {
                    storeOut(toF(aux[(long long)m * aux_ld + n]) * v,
                             &Cp[(long long)m * ldc + n]);
                } else {  // EPI_TRF2
                    storeOut(aux2[(long long)m * CA_ + n] +
                             sigf(toF(aux[(long long)m * aux_ld + n]) * v),
                             &Cp[(long long)m * ldc + n]);
                }
            }
        }
    }
}

// ---------------------------------------------------------------------------
// Host orchestration
// ---------------------------------------------------------------------------
extern "C" void kernel_launch(void* const* d_in, const int* in_sizes, int n_in,
                              void* d_out, int out_size) {
    const float* A0        = (const float*)d_in[0];
    const float* Sm        = (const float*)d_in[1];
    const float* Z         = (const float*)d_in[2];
    const float* attn_sn_w = (const float*)d_in[3];
    const float* attn_pb_w = (const float*)d_in[4];
    const float* attn_pb_b = (const float*)d_in[5];
    const float* attn_pnb_w= (const float*)d_in[6];
    const float* pair_w    = (const float*)d_in[7];
    const float* pair_b    = (const float*)d_in[8];
    const float* q_w       = (const float*)d_in[9];
    const float* q_b       = (const float*)d_in[10];
    const float* kvg_w     = (const float*)d_in[11];
    const float* bias_w    = (const float*)d_in[12];
    const float* bias_b    = (const float*)d_in[13];
    const float* ao_w      = (const float*)d_in[14];
    const float* out_w     = (const float*)d_in[15];
    const float* out_b     = (const float*)d_in[16];
    const float* tr_sn_w   = (const float*)d_in[17];
    const float* tr_pb_w   = (const float*)d_in[18];
    const float* tr_pb_b   = (const float*)d_in[19];
    const float* tr_pnb_w  = (const float*)d_in[20];
    const float* tr_a_w    = (const float*)d_in[21];
    const float* tr_s_w    = (const float*)d_in[22];
    const float* tr_s_b    = (const float*)d_in[23];
    const float* tr_b_w    = (const float*)d_in[24];
    float* OUT = (float*)d_out;

    float *an, *aout, *anew, *wbias, *sg, *adab, *sgb;
    __nv_bfloat16 *bb0, *bb1, *wbf, *shatb, *a23b, *qb, *kvgb, *obb, *bbb, *vtb, *wpbf;
    cudaGetSymbolAddress((void**)&an, g_an);
    cudaGetSymbolAddress((void**)&aout, g_aout);
    cudaGetSymbolAddress((void**)&anew, g_anew);
    cudaGetSymbolAddress((void**)&wbias, g_wbias);
    cudaGetSymbolAddress((void**)&sg, g_sg);
    cudaGetSymbolAddress((void**)&adab, g_adab);
    cudaGetSymbolAddress((void**)&sgb, g_sgb);
    cudaGetSymbolAddress((void**)&bb0, g_bb0);
    cudaGetSymbolAddress((void**)&bb1, g_bb1);
    cudaGetSymbolAddress((void**)&wbf, g_wbf);
    cudaGetSymbolAddress((void**)&shatb, g_shatb);
    cudaGetSymbolAddress((void**)&a23b, g_a23b);
    cudaGetSymbolAddress((void**)&qb, g_qb);
    cudaGetSymbolAddress((void**)&kvgb, g_kvgb);
    cudaGetSymbolAddress((void**)&obb, g_obb);
    cudaGetSymbolAddress((void**)&bbb, g_bbb);
    cudaGetSymbolAddress((void**)&vtb, g_vtb);
    cudaGetSymbolAddress((void**)&wpbf, g_wpbf);

    const int SMEM_ATTN = (128 * 56 + 2 * 128 * 56 + 2 * 48 * 136 + 2 * 128 * 136) * 2;
    cudaFuncSetAttribute(attn_fused_kernel,
                         cudaFuncAttributeMaxDynamicSharedMemorySize, SMEM_ATTN);

    // ---- conversion table ----
    CvtArgs ca;
    long long off = 0;
    int ns = 0;
    long long wo_ada1[2], wo_ada2[2], wo_q[2], wo_ao[2], wo_tra[2], wo_trb[2], wo_sg, wo_s;
    auto seg = [&](const float* s, int len, const float* sc) -> long long {
        ca.src[ns] = s; ca.scl[ns] = sc; ca.dst[ns] = wbf + off; ca.len[ns] = len;
        long long o = off; off += len; ns++; return o;
    };
    for (int l = 0; l < 2; l++) {
        wo_ada1[l] = seg(attn_pb_w  + (long long)l * CA_ * CS_, CA_ * CS_, attn_sn_w + l * CS_);
                     seg(tr_pb_w   + (long long)l * CA_ * CS_, CA_ * CS_, tr_sn_w + l * CS_);
        wo_ada2[l] = seg(attn_pnb_w + (long long)l * CA_ * CS_, CA_ * CS_, attn_sn_w + l * CS_);
                     seg(tr_pnb_w  + (long long)l * CA_ * CS_, CA_ * CS_, tr_sn_w + l * CS_);
        wo_q[l]    = seg(q_w   + (long long)l * CA_ * CA_, CA_ * CA_, nullptr);
                     seg(kvg_w + (long long)l * 3 * CA_ * CA_, 3 * CA_ * CA_, nullptr);
        wo_ao[l]   = seg(ao_w  + (long long)l * CA_ * CA_, CA_ * CA_, nullptr);
        wo_tra[l]  = seg(tr_a_w + (long long)l * 4 * CA_ * CA_, 4 * CA_ * CA_, nullptr);
        wo_trb[l]  = seg(tr_b_w + (long long)l * 2 * CA_ * CA_, 2 * CA_ * CA_, nullptr);
    }
    wo_sg = seg(out_w, CA_ * CS_, nullptr);
            seg(tr_s_w, CA_ * CS_, nullptr);
            seg(out_w + (long long)CA_ * CS_, CA_ * CS_, nullptr);
            seg(tr_s_w + (long long)CA_ * CS_, CA_ * CS_, nullptr);
    wo_s = seg(Sm, S_ * CS_, nullptr);
    ca.smod = CS_;
    ca.nseg = ns;

    cvt_kernel<<<dim3(128, ns), 256>>>(ca);
    bias_prep<<<24, 256>>>(attn_pb_b, tr_pb_b, out_b, tr_s_b, adab, sgb);
    ln_kernel<__nv_bfloat16><<<S_ / 8, 256>>>(Sm, shatb, CS_);
    zprep_kernel<<<1, 32>>>(pair_w, pair_b, bias_w, bias_b, wpbf, wbias);
    zproj_kernel<<<(S_ * S_) / 128, 256>>>(Z, wpbf, wbias, bb0, bb1);

    const __nv_bfloat16* s_bf = wbf + wo_s;

    // sgate: [og l0 | tg l0 | og l1 | tg l1]  (layer-independent)
    gemm_tc<EPI_SGATE, false, float, float><<<dim3(48, 8, 1), 256>>>(
        s_bf, wbf + wo_sg, nullptr, sgb, nullptr, nullptr, sg, nullptr,
        S_, 3072, CS_, CS_, CS_, 3072, 0, 0, 0, 0, 0, 0, 0);

    for (int l = 0; l < 2; l++) {
        const float* ain = l ? anew : A0;
        float* aoutp = l ? OUT : anew;
        const __nv_bfloat16* bbl = l ? bb1 : bb0;

        ln_kernel<float><<<S_ / 8, 256>>>(ain, an, CA_);

        // combined adaLN: a2|a3 = sigmoid((pb·sn+b)*an + pnb·sn), N=1536
        gemm_tc<EPI_ADALN, true, __nv_bfloat16, float><<<dim3(24, 8, 1), 256>>>(
            shatb, wbf + wo_ada1[l], wbf + wo_ada2[l], adab + (long long)l * 1536,
            an, nullptr, a23b, nullptr,
            S_, 1536, CS_, CS_, CS_, 1536, 0, 0, CA_, 0, 0, 0, 0);

        // combined q+kvg: N=3072, split epilogue -> qb / kvgb
        gemm_tc<EPI_SPLIT, false, __nv_bfloat16, float><<<dim3(48, 8, 1), 256>>>(
            a23b, wbf + wo_q[l], nullptr, q_b + (long long)l * CA_,
            nullptr, nullptr, qb, kvgb,
            S_, 3072, CA_, 1536, CA_, CA_, 3 * CA_, CA_, 0, 0, 0, 0, 0);

        // V transpose (plain)
        vt_kernel<<<dim3(8, 16), 256>>>(kvgb, vtb);

        // fused flash attention -> gated obb
        attn_fused_kernel<<<dim3(8, 16), 256, SMEM_ATTN>>>(kvgb, qb, vtb, bbl, obb);

        // aout = og * ((sig(g)*o) @ ao_w^T)
        gemm_tc<EPI_MULT, false, float, float><<<dim3(12, 8, 1), 256>>>(
            obb, wbf + wo_ao[l], nullptr, nullptr, sg + (long long)l * 1536, nullptr,
            aout, nullptr,
            S_, CA_, CA_, CA_, CA_, CA_, 0, 0, 3072, 0, 0, 0, 0);

        // bb = silu(a3 @ W1^T) * (a3 @ W2^T)
        gemm_tc<EPI_GLU, true, __nv_bfloat16, float><<<dim3(24, 8, 1), 256>>>(
            a23b + CA_, wbf + wo_tra[l], wbf + wo_tra[l] + (long long)2 * CA_ * CA_, nullptr,
            nullptr, nullptr, bbb, nullptr,
            S_, 2 * CA_, CA_, 1536, CA_, 2 * CA_, 0, 0, 0, 0, 0, 0, 0);

        // a_next = aout + sigmoid(tg * (bb @ tr_b_w^T))
        gemm_tc<EPI_TRF2, false, float, float><<<dim3(12, 8, 1), 256>>>(
            bbb, wbf + wo_trb[l], nullptr, nullptr,
            sg + (long long)l * 1536 + CA_, aout, aoutp, nullptr,
            S_, CA_, 2 * CA_, 2 * CA_, 2 * CA_, CA_, 0, 0, 3072, 0, 0, 0, 0);
    }
}

// round 16
// speedup vs baseline: 1.3434x; 1.3434x over previous
#include <cuda_runtime.h>
#include <cuda_bf16.h>
#include <math.h>
#include <stdint.h>

// Problem constants
#define S_   1024
#define CA_  768
#define CS_  384
#define CZ_  64
#define H_   16
#define CH_  48     // head dim
#define C3_  144    // 3*CH
#define S2_  (S_ * S_)

// ---------------------------------------------------------------------------
// Static scratch (device globals — no cudaMalloc allowed)
// ---------------------------------------------------------------------------
__device__ float g_an[S_ * CA_];           // LN(a) per layer (fp32 aux)
__device__ float g_aout[S_ * CA_];         // gated attention output
__device__ float g_anew[S_ * CA_];         // a after layer 0
__device__ float g_wbias[32];
__device__ float g_sg[S_ * 3072];          // [og l0 | tg l0 | og l1 | tg l1]
__device__ float g_adab[3072];             // stacked adaLN biases (2 layers)
__device__ float g_sgb[3072];              // stacked sgate biases

__device__ __align__(16) __nv_bfloat16 g_bb0[H_ * S2_];   // layer-0 bias [h][i][j]
__device__ __align__(16) __nv_bfloat16 g_bb1[H_ * S2_];   // layer-1 bias
__device__ __align__(16) __nv_bfloat16 g_wbf[16908288];   // all weights + s, bf16
__device__ __align__(16) __nv_bfloat16 g_shatb[S_ * CS_];
__device__ __align__(16) __nv_bfloat16 g_a23b[S_ * 1536]; // a2 | a3
__device__ __align__(16) __nv_bfloat16 g_qb[S_ * CA_];
__device__ __align__(16) __nv_bfloat16 g_kvgb[S_ * 3 * CA_];
__device__ __align__(16) __nv_bfloat16 g_obb[S_ * CA_];
__device__ __align__(16) __nv_bfloat16 g_bbb[S_ * 2 * CA_];
__device__ __align__(16) __nv_bfloat16 g_pbf[H_ * S2_];   // Pt (transposed, unnormalized)
__device__ __align__(16) __nv_bfloat16 g_vtb[H_ * CH_ * S_ + 64 * S_];  // Vt scaled (+pad)
__device__ __align__(16) __nv_bfloat16 g_wpbf[32 * 64];   // folded z-proj weights

// ---------------------------------------------------------------------------
// Helpers
// ---------------------------------------------------------------------------
__device__ __forceinline__ float sigf(float x) { return 1.0f / (1.0f + expf(-x)); }

__device__ __forceinline__ void mma_bf16(float* d, const uint32_t* a,
                                         uint32_t b0, uint32_t b1) {
    asm volatile(
        "mma.sync.aligned.m16n8k16.row.col.f32.bf16.bf16.f32 "
        "{%0,%1,%2,%3}, {%4,%5,%6,%7}, {%8,%9}, {%0,%1,%2,%3};"
        : "+f"(d[0]), "+f"(d[1]), "+f"(d[2]), "+f"(d[3])
        : "r"(a[0]), "r"(a[1]), "r"(a[2]), "r"(a[3]), "r"(b0), "r"(b1));
}

__device__ __forceinline__ void cp16(uint32_t smem, const void* g, int sbytes) {
    asm volatile("cp.async.cg.shared.global [%0], [%1], 16, %2;\n"
                 :: "r"(smem), "l"(g), "r"(sbytes));
}
#define CP_COMMIT() asm volatile("cp.async.commit_group;\n" ::)

__device__ __forceinline__ float toF(float v) { return v; }
__device__ __forceinline__ float toF(__nv_bfloat16 v) { return __bfloat162float(v); }
__device__ __forceinline__ void storeOut(float v, float* p) { *p = v; }
__device__ __forceinline__ void storeOut(float v, __nv_bfloat16* p) { *p = __float2bfloat16_rn(v); }

// ---------------------------------------------------------------------------
// Weight/act conversion fp32 -> bf16 (optionally scaling columns by scl[c])
// ---------------------------------------------------------------------------
struct CvtArgs {
    const float* src[24];
    const float* scl[24];
    __nv_bfloat16* dst[24];
    int len[24];
    int smod;
    int nseg;
};

__global__ void __launch_bounds__(256) cvt_kernel(CvtArgs a) {
    int s = blockIdx.y;
    if (s >= a.nseg) return;
    const float* src = a.src[s];
    const float* scl = a.scl[s];
    __nv_bfloat16* dst = a.dst[s];
    int n = a.len[s];
    for (long long i = (long long)(blockIdx.x * 256 + threadIdx.x) * 2; i < n;
         i += (long long)gridDim.x * 512) {
        float2 v = *(const float2*)&src[i];
        if (scl) { int c = (int)(i % a.smod); v.x *= scl[c]; v.y *= scl[c + 1]; }
        *(__nv_bfloat162*)&dst[i] = __floats2bfloat162_rn(v.x, v.y);
    }
}

// ---------------------------------------------------------------------------
// Stacked bias prep
// ---------------------------------------------------------------------------
__global__ void bias_prep(const float* __restrict__ apb_b, const float* __restrict__ trpb_b,
                          const float* __restrict__ out_b, const float* __restrict__ tr_s_b,
                          float* __restrict__ adab, float* __restrict__ sgb) {
    int i = blockIdx.x * 256 + threadIdx.x;
    if (i < 3072) {
        int l = i / 1536, n = i % 1536;
        adab[i] = (n < CA_) ? apb_b[l * CA_ + n] : trpb_b[l * CA_ + n - CA_];
    } else if (i < 6144) {
        int j = i - 3072;
        int l = j / 1536, n = j % 1536;
        sgb[j] = (n < CA_) ? out_b[l * CA_ + n] : tr_s_b[l * CA_ + n - CA_];
    }
}

// ---------------------------------------------------------------------------
// LayerNorm (no affine): one WARP per row, 8 rows/block. W % 128 == 0, W<=768.
// ---------------------------------------------------------------------------
template <typename OutT>
__global__ void __launch_bounds__(256) ln_kernel(const float* __restrict__ x,
                                                 OutT* __restrict__ y, int W) {
    int warp = threadIdx.x >> 5, lane = threadIdx.x & 31;
    long long row = (long long)blockIdx.x * 8 + warp;
    const float4* xr = (const float4*)(x + row * W);
    int npl = W >> 7;
    float4 v[6];
    float s = 0.f;
    #pragma unroll 6
    for (int i = 0; i < npl; i++) {
        v[i] = xr[lane + i * 32];
        s += v[i].x + v[i].y + v[i].z + v[i].w;
    }
    #pragma unroll
    for (int o = 16; o; o >>= 1) s += __shfl_xor_sync(0xffffffffu, s, o);
    float mean = s / (float)W;
    float vs = 0.f;
    #pragma unroll 6
    for (int i = 0; i < npl; i++) {
        float a = v[i].x - mean, b = v[i].y - mean, c = v[i].z - mean, d = v[i].w - mean;
        vs += a * a + b * b + c * c + d * d;
    }
    #pragma unroll
    for (int o = 16; o; o >>= 1) vs += __shfl_xor_sync(0xffffffffu, vs, o);
    float rstd = rsqrtf(vs / (float)W + 1e-5f);
    #pragma unroll 6
    for (int i = 0; i < npl; i++) {
        float a = (v[i].x - mean) * rstd, b = (v[i].y - mean) * rstd;
        float c = (v[i].z - mean) * rstd, d = (v[i].w - mean) * rstd;
        if constexpr (sizeof(OutT) == 4) {
            ((float4*)(y + row * W))[lane + i * 32] = make_float4(a, b, c, d);
        } else {
            uint2 u;
            __nv_bfloat162 p0 = __floats2bfloat162_rn(a, b);
            __nv_bfloat162 p1 = __floats2bfloat162_rn(c, d);
            memcpy(&u.x, &p0, 4);
            memcpy(&u.y, &p1, 4);
            ((uint2*)(y + row * W))[lane + i * 32] = u;
        }
    }
}

// ---------------------------------------------------------------------------
// z projection prep (parallel: 8 lanes per lh row, shfl reduce)
// ---------------------------------------------------------------------------
__global__ void zprep_kernel(const float* __restrict__ pw, const float* __restrict__ pb,
                             const float* __restrict__ bw, const float* __restrict__ bb,
                             __nv_bfloat16* __restrict__ Wp, float* __restrict__ Wbias) {
    int tid = threadIdx.x;            // 256 threads
    int lh = tid >> 3, part = tid & 7;
    int l = lh >> 4;
    float bs = 0.f;
    #pragma unroll
    for (int j = 0; j < 8; j++) {
        int c = part * 8 + j;
        float w = bw[lh * 64 + c];
        Wp[lh * 64 + c] = __float2bfloat16_rn(pw[l * 64 + c] * w);
        bs += pb[l * 64 + c] * w;
    }
    bs += __shfl_xor_sync(0xffffffffu, bs, 1);
    bs += __shfl_xor_sync(0xffffffffu, bs, 2);
    bs += __shfl_xor_sync(0xffffffffu, bs, 4);
    if (part == 0) Wbias[lh] = bs + bb[lh];
}

// ---------------------------------------------------------------------------
// z projection: coalesced load -> bf16 smem -> vectorized per-row LN ->
// mma (128x32x64) -> bf16 bias output [h][i*S+j] with coalesced stores.
// ---------------------------------------------------------------------------
__global__ void __launch_bounds__(256) zproj_kernel(const float* __restrict__ z,
                                                    const __nv_bfloat16* __restrict__ Wp,
                                                    const float* __restrict__ Wbias,
                                                    __nv_bfloat16* __restrict__ b0,
                                                    __nv_bfloat16* __restrict__ b1) {
    __shared__ __nv_bfloat16 zb[128][72];
    __shared__ __nv_bfloat16 wsm[32][72];
    __shared__ __nv_bfloat16 sOut[32][136];
    __shared__ float bsm[32];
    int tid = threadIdx.x;
    long long base = (long long)blockIdx.x * 8192;

    #pragma unroll
    for (int i = 0; i < 8; i++) {
        int idx = tid + i * 256;
        float4 t = *(const float4*)&z[base + (long long)idx * 4];
        int r = idx >> 4, c = (idx & 15) * 4;
        *(__nv_bfloat162*)&zb[r][c]     = __floats2bfloat162_rn(t.x, t.y);
        *(__nv_bfloat162*)&zb[r][c + 2] = __floats2bfloat162_rn(t.z, t.w);
    }
    #pragma unroll
    for (int i = 0; i < 8; i++) {
        int idx = tid + i * 256;
        wsm[idx >> 6][idx & 63] = Wp[idx];
    }
    if (tid < 32) bsm[tid] = Wbias[tid];
    __syncthreads();

    {
        int row = tid >> 1, half = tid & 1;
        uint4* zr = (uint4*)&zb[row][half * 32];
        uint4 u[4];
        float vv[32];
        float s = 0.f, s2 = 0.f;
        #pragma unroll
        for (int i = 0; i < 4; i++) {
            u[i] = zr[i];
            const __nv_bfloat162* p = (const __nv_bfloat162*)&u[i];
            #pragma unroll
            for (int w = 0; w < 4; w++) {
                float2 f = __bfloat1622float2(p[w]);
                vv[i * 8 + w * 2] = f.x; vv[i * 8 + w * 2 + 1] = f.y;
                s += f.x + f.y; s2 += f.x * f.x + f.y * f.y;
            }
        }
        s  += __shfl_xor_sync(0xffffffffu, s, 1);
        s2 += __shfl_xor_sync(0xffffffffu, s2, 1);
        float m = s * (1.f / 64.f);
        float rs = rsqrtf(s2 * (1.f / 64.f) - m * m + 1e-5f);
        #pragma unroll
        for (int i = 0; i < 4; i++) {
            __nv_bfloat162* p = (__nv_bfloat162*)&u[i];
            #pragma unroll
            for (int w = 0; w < 4; w++)
                p[w] = __floats2bfloat162_rn((vv[i * 8 + w * 2] - m) * rs,
                                             (vv[i * 8 + w * 2 + 1] - m) * rs);
            zr[i] = u[i];
        }
    }
    __syncthreads();

    int w = tid >> 5, lane = tid & 31, qr = lane >> 2, qc = lane & 3;
    float acc[4][4] = {};
    const uint32_t* zw = (const uint32_t*)&zb[0][0];
    const uint32_t* ww = (const uint32_t*)&wsm[0][0];
    #pragma unroll
    for (int kc = 0; kc < 4; kc++) {
        uint32_t af[4];
        int r = w * 16 + qr;
        af[0] = zw[r * 36 + kc * 8 + qc];
        af[1] = zw[(r + 8) * 36 + kc * 8 + qc];
        af[2] = zw[r * 36 + kc * 8 + 4 + qc];
        af[3] = zw[(r + 8) * 36 + kc * 8 + 4 + qc];
        #pragma unroll
        for (int j = 0; j < 4; j++) {
            int n = j * 8 + qr;
            mma_bf16(acc[j], af, ww[n * 36 + kc * 8 + qc], ww[n * 36 + kc * 8 + 4 + qc]);
        }
    }
    #pragma unroll
    for (int j = 0; j < 4; j++) {
        #pragma unroll
        for (int e = 0; e < 4; e++) {
            int mm = w * 16 + qr + ((e >= 2) ? 8 : 0);
            int n = j * 8 + 2 * qc + (e & 1);
            sOut[n][mm] = __float2bfloat16_rn(acc[j][e] + bsm[n]);
        }
    }
    __syncthreads();
    long long rg0 = (long long)blockIdx.x * 128;
    #pragma unroll
    for (int it = 0; it < 2; it++) {
        int lh = tid >> 3, part = (tid & 7) + it * 8;
        uint4 v = *(const uint4*)&sOut[lh][part * 8];
        __nv_bfloat16* dst = ((lh < 16) ? b0 : b1) +
                             (long long)(lh & 15) * S2_ + rg0 + part * 8;
        *(uint4*)dst = v;
    }
}

// ---------------------------------------------------------------------------
// Fused scores+softmax+Vt: per block = (head, 128 k-rows r) x all 1024 t.
// Pt[h][t][r] = exp(q[h,t]·k[h,r]/48 + bias)  (transposed, unnormalized)
// Vt[h][c][r] = v[h][r][c] / rowsum[r]        (transposed, scaled)
// Q tile now FULLY loaded (6 segs of 16B per 48-elem row).
// ---------------------------------------------------------------------------
__global__ void __launch_bounds__(256) attn_sm_kernel(
    const __nv_bfloat16* __restrict__ kvg,
    const __nv_bfloat16* __restrict__ q,
    const __nv_bfloat16* __restrict__ bias,
    __nv_bfloat16* __restrict__ Pt,
    __nv_bfloat16* __restrict__ vt) {
    const int h = blockIdx.y;
    const int bm = blockIdx.x * 128;
    const int tid = threadIdx.x, lane = tid & 31, warp = tid >> 5;
    const int wm = warp >> 1, wn = warp & 1;
    const int qr = lane >> 2, qc = lane & 3;

    extern __shared__ char smraw[];
    __nv_bfloat16* Ks  = (__nv_bfloat16*)smraw;            // [128][56]
    __nv_bfloat16* Qs  = Ks + 128 * 56;                    // [2][64][56]
    __nv_bfloat16* Bsm = Qs + 2 * 64 * 56;                 // [2][128][72]
    __nv_bfloat16* sP  = Bsm + 2 * 128 * 72;               // [64][136]
    __shared__ float rs[128];

    const __nv_bfloat16* kbase = kvg + (long long)h * S_ * C3_;
    for (int id = tid; id < 128 * 24; id += 256) {
        int r = id / 24, c2 = id % 24;
        *(__nv_bfloat162*)&Ks[r * 56 + c2 * 2] =
            *(const __nv_bfloat162*)&kbase[(long long)(bm + r) * C3_ + c2 * 2];
    }
    if (tid < 128) rs[tid] = 0.f;

    const __nv_bfloat16* qbase = q + (long long)h * S_ * CH_;
    const __nv_bfloat16* bbase = bias + (long long)h * S2_;
    __nv_bfloat16* ptbase = Pt + (long long)h * S2_;
    uint32_t qS = (uint32_t)__cvta_generic_to_shared(Qs);
    uint32_t bS = (uint32_t)__cvta_generic_to_shared(Bsm);

    auto issue = [&](int st, int tc) {
        // Q tile: 64 rows x 6 segs of 16B = FULL 48 elements per row
        #pragma unroll
        for (int i = 0; i < 2; i++) {
            int id = tid + i * 256;
            if (id < 384) {
                int t = id / 6, seg = id % 6;
                cp16(qS + st * 64 * 112 + t * 112 + seg * 16,
                     qbase + (long long)(tc * 64 + t) * CH_ + seg * 8, 16);
            }
        }
        // bias tile: 128 rows x 8 segs (64 cols, full)
        #pragma unroll
        for (int i = 0; i < 4; i++) {
            int id = tid + i * 256;
            int r = id >> 3, seg = id & 7;
            cp16(bS + st * 128 * 144 + r * 144 + seg * 16,
                 bbase + (long long)(bm + r) * S_ + tc * 64 + seg * 8, 16);
        }
    };

    float rowacc[2][2] = {};
    issue(0, 0);
    CP_COMMIT();

    for (int tc = 0; tc < 16; tc++) {
        asm volatile("cp.async.wait_group 0;\n" ::);
        __syncthreads();
        if (tc + 1 < 16) issue((tc + 1) & 1, tc + 1);
        CP_COMMIT();
        int st = tc & 1;
        float acc[2][4][4] = {};
        #pragma unroll
        for (int ks = 0; ks < 3; ks++) {
            uint32_t af[2][4];
            #pragma unroll
            for (int i = 0; i < 2; i++) {
                int r = wm * 32 + i * 16 + qr;
                const uint32_t* a0 = (const uint32_t*)&Ks[r * 56];
                const uint32_t* a8 = (const uint32_t*)&Ks[(r + 8) * 56];
                af[i][0] = a0[ks * 8 + qc];
                af[i][1] = a8[ks * 8 + qc];
                af[i][2] = a0[ks * 8 + 4 + qc];
                af[i][3] = a8[ks * 8 + 4 + qc];
            }
            #pragma unroll
            for (int j = 0; j < 4; j++) {
                int n = wn * 32 + j * 8 + qr;
                const uint32_t* br = (const uint32_t*)&Qs[st * 64 * 56 + n * 56];
                uint32_t b0 = br[ks * 8 + qc];
                uint32_t b1 = br[ks * 8 + 4 + qc];
                #pragma unroll
                for (int i = 0; i < 2; i++) mma_bf16(acc[i][j], af[i], b0, b1);
            }
        }
        #pragma unroll
        for (int i = 0; i < 2; i++) {
            #pragma unroll
            for (int eh = 0; eh < 2; eh++) {
                int ml = wm * 32 + i * 16 + qr + eh * 8;
                const __nv_bfloat16* brow = &Bsm[st * 128 * 72 + ml * 72];
                float part = 0.f;
                #pragma unroll
                for (int j = 0; j < 4; j++) {
                    int nl = wn * 32 + j * 8 + 2 * qc;
                    __nv_bfloat162 bb = *(const __nv_bfloat162*)&brow[nl];
                    float v0 = acc[i][j][eh * 2 + 0] * (1.f / 48.f) + toF(bb.x);
                    float v1 = acc[i][j][eh * 2 + 1] * (1.f / 48.f) + toF(bb.y);
                    float e0 = __expf(v0), e1 = __expf(v1);
                    sP[nl * 136 + ml]       = __float2bfloat16_rn(e0);
                    sP[(nl + 1) * 136 + ml] = __float2bfloat16_rn(e1);
                    part += e0 + e1;
                }
                rowacc[i][eh] += part;
            }
        }
        __syncthreads();
        #pragma unroll
        for (int it = 0; it < 4; it++) {
            int id = tid + it * 256;
            int trow = id >> 4, chunk = id & 15;
            uint4 v = *(const uint4*)&sP[trow * 136 + chunk * 8];
            *(uint4*)&ptbase[(long long)(tc * 64 + trow) * S_ + bm + chunk * 8] = v;
        }
    }
    #pragma unroll
    for (int i = 0; i < 2; i++) {
        #pragma unroll
        for (int eh = 0; eh < 2; eh++) {
            float v = rowacc[i][eh];
            v += __shfl_xor_sync(0xffffffffu, v, 1);
            v += __shfl_xor_sync(0xffffffffu, v, 2);
            if (qc == 0) atomicAdd(&rs[wm * 32 + i * 16 + qr + eh * 8], v);
        }
    }
    __syncthreads();

    // ---- fused Vt: scale V rows by 1/rowsum, transpose, store ----
    {
        __nv_bfloat16* sv = sP;   // reuse staging (48x136 <= 64x136)
        const __nv_bfloat16* vbase = kvg + (long long)h * S_ * C3_ + CH_;
        for (int id = tid; id < 128 * 24; id += 256) {
            int r = id / 24, c2 = id % 24;
            __nv_bfloat162 v = *(const __nv_bfloat162*)&vbase[(long long)(bm + r) * C3_ + 2 * c2];
            float sc = 1.0f / rs[r];
            sv[(2 * c2) * 136 + r]     = __float2bfloat16_rn(toF(v.x) * sc);
            sv[(2 * c2 + 1) * 136 + r] = __float2bfloat16_rn(toF(v.y) * sc);
        }
        __syncthreads();
        for (int id = tid; id < 48 * 16; id += 256) {
            int c = id >> 4, chunk = id & 15;
            *(uint4*)&vt[(long long)h * CH_ * S_ + (long long)c * S_ + bm + chunk * 8] =
                *(const uint4*)&sv[c * 136 + chunk * 8];
        }
    }
}

// ---------------------------------------------------------------------------
// Tensor-core bf16 GEMM (NT):  C[m,n] = sum_k A[m,k] * B[n,k]
// cp.async multi-stage ring, one sync per k-chunk.
// Block tile 128x64, BK=32, 256 threads (8 warps, 4x2), warp tile 32x32.
// ---------------------------------------------------------------------------
enum { EPI_PLAIN = 0, EPI_GSIG = 2, EPI_ADALN = 5, EPI_GLU = 6,
       EPI_SPLIT = 7, EPI_SGATE = 8, EPI_MULT = 9, EPI_TRF2 = 10 };

template <int EPI, bool DUAL, typename OutT, typename AuxT>
__global__ void __launch_bounds__(256) gemm_tc(
    const __nv_bfloat16* __restrict__ A, const __nv_bfloat16* __restrict__ B1,
    const __nv_bfloat16* __restrict__ B2, const float* __restrict__ bias,
    const AuxT* __restrict__ aux, const float* __restrict__ aux2,
    OutT* __restrict__ Cp, OutT* __restrict__ Cp2,
    int M, int N, int K, int lda, int ldb, int ldc, int ldc2, int nsplit, int aux_ld,
    long long sA, long long sB, long long sC, long long sAux) {
    constexpr int NST = DUAL ? 2 : 3;
    const int tid = threadIdx.x;
    const int lane = tid & 31, warp = tid >> 5;
    const int wm = warp >> 1, wn = warp & 1;
    const int bm = blockIdx.y * 128, bn = blockIdx.x * 64;
    const int bz = blockIdx.z;
    A += bz * sA;
    B1 += bz * sB;
    if constexpr (DUAL) B2 += bz * sB;
    Cp += bz * sC;
    if (aux) aux += bz * sAux;

    __shared__ __nv_bfloat16 As[NST][128][40];
    __shared__ __nv_bfloat16 Bs1[NST][64][40];
    __shared__ __nv_bfloat16 Bs2[DUAL ? NST : 1][64][40];

    float acc1[2][4][4] = {};
    float acc2[2][4][4] = {};
    const int qr = lane >> 2, qc = lane & 3;
    const int nk = (K + 31) / 32;

    auto do_mma = [&](int st) {
        #pragma unroll
        for (int ks = 0; ks < 2; ks++) {
            uint32_t af[2][4];
            #pragma unroll
            for (int i = 0; i < 2; i++) {
                int r = wm * 32 + i * 16 + qr;
                const uint32_t* arow  = (const uint32_t*)&As[st][r][0];
                const uint32_t* arow8 = (const uint32_t*)&As[st][r + 8][0];
                af[i][0] = arow[ks * 8 + qc];
                af[i][1] = arow8[ks * 8 + qc];
                af[i][2] = arow[ks * 8 + 4 + qc];
                af[i][3] = arow8[ks * 8 + 4 + qc];
            }
            #pragma unroll
            for (int j = 0; j < 4; j++) {
                int n = wn * 32 + j * 8 + qr;
                const uint32_t* brow = (const uint32_t*)&Bs1[st][n][0];
                uint32_t b0 = brow[ks * 8 + qc];
                uint32_t b1 = brow[ks * 8 + 4 + qc];
                #pragma unroll
                for (int i = 0; i < 2; i++) mma_bf16(acc1[i][j], af[i], b0, b1);
                if constexpr (DUAL) {
                    const uint32_t* brow2 = (const uint32_t*)&Bs2[st][n][0];
                    uint32_t c0 = brow2[ks * 8 + qc];
                    uint32_t c1 = brow2[ks * 8 + 4 + qc];
                    #pragma unroll
                    for (int i = 0; i < 2; i++) mma_bf16(acc2[i][j], af[i], c0, c1);
                }
            }
        }
    };

    uint32_t aBase = (uint32_t)__cvta_generic_to_shared(&As[0][0][0]);
    uint32_t bBase = (uint32_t)__cvta_generic_to_shared(&Bs1[0][0][0]);
    uint32_t b2Base = 0;
    if constexpr (DUAL) b2Base = (uint32_t)__cvta_generic_to_shared(&Bs2[0][0][0]);

    auto issue = [&](int st, int k0) {
        #pragma unroll
        for (int i = 0; i < 2; i++) {
            int id = tid + i * 256;
            int r = id >> 2, cp4 = id & 3;
            int kk = k0 + cp4 * 8;
            const __nv_bfloat16* src = A + (long long)(bm + r) * lda + kk;
            int sb = (kk < K) ? 16 : 0;
            if (!sb) src = A;
            cp16(aBase + st * 128 * 80 + r * 80 + cp4 * 16, src, sb);
        }
        {
            int r = tid >> 2, cp4 = tid & 3;
            int kk = k0 + cp4 * 8;
            int sb = (kk < K) ? 16 : 0;
            const __nv_bfloat16* src = B1 + (long long)(bn + r) * ldb + kk;
            if (!sb) src = B1;
            cp16(bBase + st * 64 * 80 + r * 80 + cp4 * 16, src, sb);
            if constexpr (DUAL) {
                const __nv_bfloat16* src2 = B2 + (long long)(bn + r) * ldb + kk;
                if (!sb) src2 = B2;
                cp16(b2Base + st * 64 * 80 + r * 80 + cp4 * 16, src2, sb);
            }
        }
    };

    #pragma unroll
    for (int p = 0; p < NST - 1; p++) {
        if (p < nk) issue(p, p * 32);
        CP_COMMIT();
    }
    for (int ic = 0; ic < nk; ic++) {
        if constexpr (NST == 3) asm volatile("cp.async.wait_group 1;\n" ::);
        else                    asm volatile("cp.async.wait_group 0;\n" ::);
        __syncthreads();
        int pn = ic + NST - 1;
        if (pn < nk) issue(pn % NST, pn * 32);
        CP_COMMIT();
        do_mma(ic % NST);
    }

    // ---- epilogue ----
    #pragma unroll
    for (int i = 0; i < 2; i++) {
        #pragma unroll
        for (int j = 0; j < 4; j++) {
            int m0 = bm + wm * 32 + i * 16 + qr;
            int n0 = bn + wn * 32 + j * 8 + 2 * qc;
            #pragma unroll
            for (int e = 0; e < 4; e++) {
                int m = m0 + ((e >= 2) ? 8 : 0);
                int n = n0 + (e & 1);
                if (n >= N) continue;
                float v = acc1[i][j][e];
                if constexpr (EPI == EPI_PLAIN) {
                    storeOut(v + (bias ? bias[n] : 0.f), &Cp[(long long)m * ldc + n]);
                } else if constexpr (EPI == EPI_GSIG) {
                    storeOut(sigf(toF(aux[(long long)m * aux_ld + n])) * v,
                             &Cp[(long long)m * ldc + n]);
                } else if constexpr (EPI == EPI_ADALN) {
                    int na = (n >= CA_) ? n - CA_ : n;
                    storeOut(sigf((v + bias[n]) * toF(aux[(long long)m * aux_ld + na]) +
                                  acc2[i][j][e]),
                             &Cp[(long long)m * ldc + n]);
                } else if constexpr (EPI == EPI_GLU) {
                    storeOut(v * sigf(v) * acc2[i][j][e], &Cp[(long long)m * ldc + n]);
                } else if constexpr (EPI == EPI_SPLIT) {
                    float out = v + ((n < nsplit) ? bias[n] : 0.f);
                    if (n < nsplit) storeOut(out, &Cp[(long long)m * ldc + n]);
                    else            storeOut(out, &Cp2[(long long)m * ldc2 + (n - nsplit)]);
                } else if constexpr (EPI == EPI_SGATE) {
                    bool sg = (((bn / 768) & 1) == 0);
                    float out = v + bias[n];
                    storeOut(sg ? sigf(out) : out, &Cp[(long long)m * ldc + n]);
                } else if constexpr (EPI == EPI_MULT) {
                    storeOut(toF(aux[(long long)m * aux_ld + n]) * v,
                             &Cp[(long long)m * ldc + n]);
                } else {  // EPI_TRF2
                    storeOut(aux2[(long long)m * CA_ + n] +
                             sigf(toF(aux[(long long)m * aux_ld + n]) * v),
                             &Cp[(long long)m * ldc + n]);
                }
            }
        }
    }
}

// ---------------------------------------------------------------------------
// Host orchestration
// ---------------------------------------------------------------------------
extern "C" void kernel_launch(void* const* d_in, const int* in_sizes, int n_in,
                              void* d_out, int out_size) {
    const float* A0        = (const float*)d_in[0];
    const float* Sm        = (const float*)d_in[1];
    const float* Z         = (const float*)d_in[2];
    const float* attn_sn_w = (const float*)d_in[3];
    const float* attn_pb_w = (const float*)d_in[4];
    const float* attn_pb_b = (const float*)d_in[5];
    const float* attn_pnb_w= (const float*)d_in[6];
    const float* pair_w    = (const float*)d_in[7];
    const float* pair_b    = (const float*)d_in[8];
    const float* q_w       = (const float*)d_in[9];
    const float* q_b       = (const float*)d_in[10];
    const float* kvg_w     = (const float*)d_in[11];
    const float* bias_w    = (const float*)d_in[12];
    const float* bias_b    = (const float*)d_in[13];
    const float* ao_w      = (const float*)d_in[14];
    const float* out_w     = (const float*)d_in[15];
    const float* out_b     = (const float*)d_in[16];
    const float* tr_sn_w   = (const float*)d_in[17];
    const float* tr_pb_w   = (const float*)d_in[18];
    const float* tr_pb_b   = (const float*)d_in[19];
    const float* tr_pnb_w  = (const float*)d_in[20];
    const float* tr_a_w    = (const float*)d_in[21];
    const float* tr_s_w    = (const float*)d_in[22];
    const float* tr_s_b    = (const float*)d_in[23];
    const float* tr_b_w    = (const float*)d_in[24];
    float* OUT = (float*)d_out;

    float *an, *aout, *anew, *wbias, *sg, *adab, *sgb;
    __nv_bfloat16 *bb0, *bb1, *wbf, *shatb, *a23b, *qb, *kvgb, *obb, *bbb, *pbf, *vtb, *wpbf;
    cudaGetSymbolAddress((void**)&an, g_an);
    cudaGetSymbolAddress((void**)&aout, g_aout);
    cudaGetSymbolAddress((void**)&anew, g_anew);
    cudaGetSymbolAddress((void**)&wbias, g_wbias);
    cudaGetSymbolAddress((void**)&sg, g_sg);
    cudaGetSymbolAddress((void**)&adab, g_adab);
    cudaGetSymbolAddress((void**)&sgb, g_sgb);
    cudaGetSymbolAddress((void**)&bb0, g_bb0);
    cudaGetSymbolAddress((void**)&bb1, g_bb1);
    cudaGetSymbolAddress((void**)&wbf, g_wbf);
    cudaGetSymbolAddress((void**)&shatb, g_shatb);
    cudaGetSymbolAddress((void**)&a23b, g_a23b);
    cudaGetSymbolAddress((void**)&qb, g_qb);
    cudaGetSymbolAddress((void**)&kvgb, g_kvgb);
    cudaGetSymbolAddress((void**)&obb, g_obb);
    cudaGetSymbolAddress((void**)&bbb, g_bbb);
    cudaGetSymbolAddress((void**)&pbf, g_pbf);
    cudaGetSymbolAddress((void**)&vtb, g_vtb);
    cudaGetSymbolAddress((void**)&wpbf, g_wpbf);

    cudaFuncSetAttribute(attn_sm_kernel, cudaFuncAttributeMaxDynamicSharedMemorySize, 82944);

    // ---- conversion table ----
    CvtArgs ca;
    long long off = 0;
    int ns = 0;
    long long wo_ada1[2], wo_ada2[2], wo_q[2], wo_ao[2], wo_tra[2], wo_trb[2], wo_sg, wo_s;
    auto seg = [&](const float* s, int len, const float* sc) -> long long {
        ca.src[ns] = s; ca.scl[ns] = sc; ca.dst[ns] = wbf + off; ca.len[ns] = len;
        long long o = off; off += len; ns++; return o;
    };
    for (int l = 0; l < 2; l++) {
        wo_ada1[l] = seg(attn_pb_w  + (long long)l * CA_ * CS_, CA_ * CS_, attn_sn_w + l * CS_);
                     seg(tr_pb_w   + (long long)l * CA_ * CS_, CA_ * CS_, tr_sn_w + l * CS_);
        wo_ada2[l] = seg(attn_pnb_w + (long long)l * CA_ * CS_, CA_ * CS_, attn_sn_w + l * CS_);
                     seg(tr_pnb_w  + (long long)l * CA_ * CS_, CA_ * CS_, tr_sn_w + l * CS_);
        wo_q[l]    = seg(q_w   + (long long)l * CA_ * CA_, CA_ * CA_, nullptr);
                     seg(kvg_w + (long long)l * 3 * CA_ * CA_, 3 * CA_ * CA_, nullptr);
        wo_ao[l]   = seg(ao_w  + (long long)l * CA_ * CA_, CA_ * CA_, nullptr);
        wo_tra[l]  = seg(tr_a_w + (long long)l * 4 * CA_ * CA_, 4 * CA_ * CA_, nullptr);
        wo_trb[l]  = seg(tr_b_w + (long long)l * 2 * CA_ * CA_, 2 * CA_ * CA_, nullptr);
    }
    wo_sg = seg(out_w, CA_ * CS_, nullptr);
            seg(tr_s_w, CA_ * CS_, nullptr);
            seg(out_w + (long long)CA_ * CS_, CA_ * CS_, nullptr);
            seg(tr_s_w + (long long)CA_ * CS_, CA_ * CS_, nullptr);
    wo_s = seg(Sm, S_ * CS_, nullptr);
    ca.smod = CS_;
    ca.nseg = ns;

    cvt_kernel<<<dim3(128, ns), 256>>>(ca);
    bias_prep<<<24, 256>>>(attn_pb_b, tr_pb_b, out_b, tr_s_b, adab, sgb);
    ln_kernel<__nv_bfloat16><<<S_ / 8, 256>>>(Sm, shatb, CS_);
    zprep_kernel<<<1, 256>>>(pair_w, pair_b, bias_w, bias_b, wpbf, wbias);
    zproj_kernel<<<(S_ * S_) / 128, 256>>>(Z, wpbf, wbias, bb0, bb1);

    const __nv_bfloat16* s_bf = wbf + wo_s;

    // sgate: [og l0 | tg l0 | og l1 | tg l1]  (layer-independent)
    gemm_tc<EPI_SGATE, false, float, float><<<dim3(48, 8, 1), 256>>>(
        s_bf, wbf + wo_sg, nullptr, sgb, nullptr, nullptr, sg, nullptr,
        S_, 3072, CS_, CS_, CS_, 3072, 0, 0, 0, 0, 0, 0, 0);

    for (int l = 0; l < 2; l++) {
        const float* ain = l ? anew : A0;
        float* aoutp = l ? OUT : anew;
        const __nv_bfloat16* bbl = l ? bb1 : bb0;

        ln_kernel<float><<<S_ / 8, 256>>>(ain, an, CA_);

        // combined adaLN: a2|a3 = sigmoid((pb·sn+b)*an + pnb·sn), N=1536
        gemm_tc<EPI_ADALN, true, __nv_bfloat16, float><<<dim3(24, 8, 1), 256>>>(
            shatb, wbf + wo_ada1[l], wbf + wo_ada2[l], adab + (long long)l * 1536,
            an, nullptr, a23b, nullptr,
            S_, 1536, CS_, CS_, CS_, 1536, 0, 0, CA_, 0, 0, 0, 0);

        // combined q+kvg: N=3072, split epilogue -> qb / kvgb
        gemm_tc<EPI_SPLIT, false, __nv_bfloat16, float><<<dim3(48, 8, 1), 256>>>(
            a23b, wbf + wo_q[l], nullptr, q_b + (long long)l * CA_,
            nullptr, nullptr, qb, kvgb,
            S_, 3072, CA_, 1536, CA_, CA_, 3 * CA_, CA_, 0, 0, 0, 0, 0);

        // fused scores + softmax + Vt
        attn_sm_kernel<<<dim3(8, 16), 256, 82944>>>(kvgb, qb, bbl, pbf, vtb);

        // o[t,c] = sum_r Pt[t,r]*Vt[c,r];  fused sigmoid(g)*o
        gemm_tc<EPI_GSIG, false, __nv_bfloat16, __nv_bfloat16><<<dim3(1, 8, 16), 256>>>(
            pbf, vtb, nullptr, nullptr, kvgb + 2 * CH_, nullptr, obb, nullptr,
            S_, CH_, S_, S_, S_, CH_, 0, 0, C3_,
            (long long)S2_, (long long)CH_ * S_, (long long)S_ * CH_,
            (long long)S_ * C3_);

        // aout = og * ((sig(g)*o) @ ao_w^T)
        gemm_tc<EPI_MULT, false, float, float><<<dim3(12, 8, 1), 256>>>(
            obb, wbf + wo_ao[l], nullptr, nullptr, sg + (long long)l * 1536, nullptr,
            aout, nullptr,
            S_, CA_, CA_, CA_, CA_, CA_, 0, 0, 3072, 0, 0, 0, 0);

        // bb = silu(a3 @ W1^T) * (a3 @ W2^T)
        gemm_tc<EPI_GLU, true, __nv_bfloat16, float><<<dim3(24, 8, 1), 256>>>(
            a23b + CA_, wbf + wo_tra[l], wbf + wo_tra[l] + (long long)2 * CA_ * CA_, nullptr,
            nullptr, nullptr, bbb, nullptr,
            S_, 2 * CA_, CA_, 1536, CA_, 2 * CA_, 0, 0, 0, 0, 0, 0, 0);

        // a_next = aout + sigmoid(tg * (bb @ tr_b_w^T))
        gemm_tc<EPI_TRF2, false, float, float><<<dim3(12, 8, 1), 256>>>(
            bbb, wbf + wo_trb[l], nullptr, nullptr,
            sg + (long long)l * 1536 + CA_, aout, aoutp, nullptr,
            S_, CA_, 2 * CA_, 2 * CA_, 2 * CA_, CA_, 0, 0, 3072, 0, 0, 0, 0);
    }
}

// round 17
// speedup vs baseline: 1.3956x; 1.0388x over previous
#include <cuda_runtime.h>
#include <cuda_bf16.h>
#include <math.h>
#include <stdint.h>

// Problem constants
#define S_   1024
#define CA_  768
#define CS_  384
#define CZ_  64
#define H_   16
#define CH_  48     // head dim
#define C3_  144    // 3*CH
#define S2_  (S_ * S_)

// ---------------------------------------------------------------------------
// Static scratch (device globals — no cudaMalloc allowed)
// ---------------------------------------------------------------------------
__device__ float g_an[S_ * CA_];           // LN(a) per layer (fp32 aux)
__device__ float g_aout[S_ * CA_];         // gated attention output
__device__ float g_anew[S_ * CA_];         // a after layer 0
__device__ float g_wbias[32];
__device__ float g_sg[S_ * 3072];          // [og l0 | tg l0 | og l1 | tg l1]
__device__ float g_adab[3072];             // stacked adaLN biases (2 layers)
__device__ float g_sgb[3072];              // stacked sgate biases

__device__ __align__(16) __nv_bfloat16 g_bb0[H_ * S2_];   // layer-0 bias [h][i][j]
__device__ __align__(16) __nv_bfloat16 g_bb1[H_ * S2_];   // layer-1 bias
__device__ __align__(16) __nv_bfloat16 g_wbf[16908288];   // all weights + s, bf16
__device__ __align__(16) __nv_bfloat16 g_shatb[S_ * CS_];
__device__ __align__(16) __nv_bfloat16 g_a23b[S_ * 1536]; // a2 | a3
__device__ __align__(16) __nv_bfloat16 g_qb[S_ * CA_];
__device__ __align__(16) __nv_bfloat16 g_kvgb[S_ * 3 * CA_];
__device__ __align__(16) __nv_bfloat16 g_obb[S_ * CA_];
__device__ __align__(16) __nv_bfloat16 g_bbb[S_ * 2 * CA_];
__device__ __align__(16) __nv_bfloat16 g_pbf[H_ * S2_];   // Pt (transposed, unnormalized)
__device__ __align__(16) __nv_bfloat16 g_vtb[H_ * CH_ * S_ + 64 * S_];  // Vt scaled (+pad)
__device__ __align__(16) __nv_bfloat16 g_wpbf[32 * 64];   // folded z-proj weights

// ---------------------------------------------------------------------------
// Helpers
// ---------------------------------------------------------------------------
__device__ __forceinline__ float sigf(float x) { return 1.0f / (1.0f + expf(-x)); }

__device__ __forceinline__ void mma_bf16(float* d, const uint32_t* a,
                                         uint32_t b0, uint32_t b1) {
    asm volatile(
        "mma.sync.aligned.m16n8k16.row.col.f32.bf16.bf16.f32 "
        "{%0,%1,%2,%3}, {%4,%5,%6,%7}, {%8,%9}, {%0,%1,%2,%3};"
        : "+f"(d[0]), "+f"(d[1]), "+f"(d[2]), "+f"(d[3])
        : "r"(a[0]), "r"(a[1]), "r"(a[2]), "r"(a[3]), "r"(b0), "r"(b1));
}

__device__ __forceinline__ void ldsm_x4(uint32_t* r, uint32_t saddr) {
    asm volatile("ldmatrix.sync.aligned.m8n8.x4.shared.b16 {%0,%1,%2,%3}, [%4];\n"
                 : "=r"(r[0]), "=r"(r[1]), "=r"(r[2]), "=r"(r[3]) : "r"(saddr));
}

__device__ __forceinline__ void ldsm_x2(uint32_t* r, uint32_t saddr) {
    asm volatile("ldmatrix.sync.aligned.m8n8.x2.shared.b16 {%0,%1}, [%2];\n"
                 : "=r"(r[0]), "=r"(r[1]) : "r"(saddr));
}

__device__ __forceinline__ void cp16(uint32_t smem, const void* g, int sbytes) {
    asm volatile("cp.async.cg.shared.global [%0], [%1], 16, %2;\n"
                 :: "r"(smem), "l"(g), "r"(sbytes));
}
#define CP_COMMIT() asm volatile("cp.async.commit_group;\n" ::)

__device__ __forceinline__ float toF(float v) { return v; }
__device__ __forceinline__ float toF(__nv_bfloat16 v) { return __bfloat162float(v); }
__device__ __forceinline__ void storeOut(float v, float* p) { *p = v; }
__device__ __forceinline__ void storeOut(float v, __nv_bfloat16* p) { *p = __float2bfloat16_rn(v); }

// ---------------------------------------------------------------------------
// Weight/act conversion fp32 -> bf16 (optionally scaling columns by scl[c])
// ---------------------------------------------------------------------------
struct CvtArgs {
    const float* src[24];
    const float* scl[24];
    __nv_bfloat16* dst[24];
    int len[24];
    int smod;
    int nseg;
};

__global__ void __launch_bounds__(256) cvt_kernel(CvtArgs a) {
    int s = blockIdx.y;
    if (s >= a.nseg) return;
    const float* src = a.src[s];
    const float* scl = a.scl[s];
    __nv_bfloat16* dst = a.dst[s];
    int n = a.len[s];
    for (long long i = (long long)(blockIdx.x * 256 + threadIdx.x) * 2; i < n;
         i += (long long)gridDim.x * 512) {
        float2 v = *(const float2*)&src[i];
        if (scl) { int c = (int)(i % a.smod); v.x *= scl[c]; v.y *= scl[c + 1]; }
        *(__nv_bfloat162*)&dst[i] = __floats2bfloat162_rn(v.x, v.y);
    }
}

// ---------------------------------------------------------------------------
// Stacked bias prep + z projection weight prep (merged; block 24 = zprep)
// ---------------------------------------------------------------------------
__global__ void bias_prep(const float* __restrict__ apb_b, const float* __restrict__ trpb_b,
                          const float* __restrict__ out_b, const float* __restrict__ tr_s_b,
                          float* __restrict__ adab, float* __restrict__ sgb,
                          const float* __restrict__ pw, const float* __restrict__ pb,
                          const float* __restrict__ bw, const float* __restrict__ bb,
                          __nv_bfloat16* __restrict__ Wp, float* __restrict__ Wbias) {
    if (blockIdx.x == 24) {
        int tid = threadIdx.x;            // 256 threads
        int lh = tid >> 3, part = tid & 7;
        int l = lh >> 4;
        float bs = 0.f;
        #pragma unroll
        for (int j = 0; j < 8; j++) {
            int c = part * 8 + j;
            float w = bw[lh * 64 + c];
            Wp[lh * 64 + c] = __float2bfloat16_rn(pw[l * 64 + c] * w);
            bs += pb[l * 64 + c] * w;
        }
        bs += __shfl_xor_sync(0xffffffffu, bs, 1);
        bs += __shfl_xor_sync(0xffffffffu, bs, 2);
        bs += __shfl_xor_sync(0xffffffffu, bs, 4);
        if (part == 0) Wbias[lh] = bs + bb[lh];
        return;
    }
    int i = blockIdx.x * 256 + threadIdx.x;
    if (i < 3072) {
        int l = i / 1536, n = i % 1536;
        adab[i] = (n < CA_) ? apb_b[l * CA_ + n] : trpb_b[l * CA_ + n - CA_];
    } else if (i < 6144) {
        int j = i - 3072;
        int l = j / 1536, n = j % 1536;
        sgb[j] = (n < CA_) ? out_b[l * CA_ + n] : tr_s_b[l * CA_ + n - CA_];
    }
}

// ---------------------------------------------------------------------------
// LayerNorm (no affine): one WARP per row, 8 rows/block. W % 128 == 0, W<=768.
// ---------------------------------------------------------------------------
template <typename OutT>
__global__ void __launch_bounds__(256) ln_kernel(const float* __restrict__ x,
                                                 OutT* __restrict__ y, int W) {
    int warp = threadIdx.x >> 5, lane = threadIdx.x & 31;
    long long row = (long long)blockIdx.x * 8 + warp;
    const float4* xr = (const float4*)(x + row * W);
    int npl = W >> 7;
    float4 v[6];
    float s = 0.f;
    #pragma unroll 6
    for (int i = 0; i < npl; i++) {
        v[i] = xr[lane + i * 32];
        s += v[i].x + v[i].y + v[i].z + v[i].w;
    }
    #pragma unroll
    for (int o = 16; o; o >>= 1) s += __shfl_xor_sync(0xffffffffu, s, o);
    float mean = s / (float)W;
    float vs = 0.f;
    #pragma unroll 6
    for (int i = 0; i < npl; i++) {
        float a = v[i].x - mean, b = v[i].y - mean, c = v[i].z - mean, d = v[i].w - mean;
        vs += a * a + b * b + c * c + d * d;
    }
    #pragma unroll
    for (int o = 16; o; o >>= 1) vs += __shfl_xor_sync(0xffffffffu, vs, o);
    float rstd = rsqrtf(vs / (float)W + 1e-5f);
    #pragma unroll 6
    for (int i = 0; i < npl; i++) {
        float a = (v[i].x - mean) * rstd, b = (v[i].y - mean) * rstd;
        float c = (v[i].z - mean) * rstd, d = (v[i].w - mean) * rstd;
        if constexpr (sizeof(OutT) == 4) {
            ((float4*)(y + row * W))[lane + i * 32] = make_float4(a, b, c, d);
        } else {
            uint2 u;
            __nv_bfloat162 p0 = __floats2bfloat162_rn(a, b);
            __nv_bfloat162 p1 = __floats2bfloat162_rn(c, d);
            memcpy(&u.x, &p0, 4);
            memcpy(&u.y, &p1, 4);
            ((uint2*)(y + row * W))[lane + i * 32] = u;
        }
    }
}

// ---------------------------------------------------------------------------
// z projection: coalesced load -> bf16 smem -> vectorized per-row LN ->
// mma (128x32x64) -> bf16 bias output [h][i*S+j] with coalesced stores.
// ---------------------------------------------------------------------------
__global__ void __launch_bounds__(256) zproj_kernel(const float* __restrict__ z,
                                                    const __nv_bfloat16* __restrict__ Wp,
                                                    const float* __restrict__ Wbias,
                                                    __nv_bfloat16* __restrict__ b0,
                                                    __nv_bfloat16* __restrict__ b1) {
    __shared__ __nv_bfloat16 zb[128][72];
    __shared__ __nv_bfloat16 wsm[32][72];
    __shared__ __nv_bfloat16 sOut[32][136];
    __shared__ float bsm[32];
    int tid = threadIdx.x;
    long long base = (long long)blockIdx.x * 8192;

    #pragma unroll
    for (int i = 0; i < 8; i++) {
        int idx = tid + i * 256;
        float4 t = *(const float4*)&z[base + (long long)idx * 4];
        int r = idx >> 4, c = (idx & 15) * 4;
        *(__nv_bfloat162*)&zb[r][c]     = __floats2bfloat162_rn(t.x, t.y);
        *(__nv_bfloat162*)&zb[r][c + 2] = __floats2bfloat162_rn(t.z, t.w);
    }
    #pragma unroll
    for (int i = 0; i < 8; i++) {
        int idx = tid + i * 256;
        wsm[idx >> 6][idx & 63] = Wp[idx];
    }
    if (tid < 32) bsm[tid] = Wbias[tid];
    __syncthreads();

    {
        int row = tid >> 1, half = tid & 1;
        uint4* zr = (uint4*)&zb[row][half * 32];
        uint4 u[4];
        float vv[32];
        float s = 0.f, s2 = 0.f;
        #pragma unroll
        for (int i = 0; i < 4; i++) {
            u[i] = zr[i];
            const __nv_bfloat162* p = (const __nv_bfloat162*)&u[i];
            #pragma unroll
            for (int w = 0; w < 4; w++) {
                float2 f = __bfloat1622float2(p[w]);
                vv[i * 8 + w * 2] = f.x; vv[i * 8 + w * 2 + 1] = f.y;
                s += f.x + f.y; s2 += f.x * f.x + f.y * f.y;
            }
        }
        s  += __shfl_xor_sync(0xffffffffu, s, 1);
        s2 += __shfl_xor_sync(0xffffffffu, s2, 1);
        float m = s * (1.f / 64.f);
        float rs = rsqrtf(s2 * (1.f / 64.f) - m * m + 1e-5f);
        #pragma unroll
        for (int i = 0; i < 4; i++) {
            __nv_bfloat162* p = (__nv_bfloat162*)&u[i];
            #pragma unroll
            for (int w = 0; w < 4; w++)
                p[w] = __floats2bfloat162_rn((vv[i * 8 + w * 2] - m) * rs,
                                             (vv[i * 8 + w * 2 + 1] - m) * rs);
            zr[i] = u[i];
        }
    }
    __syncthreads();

    int w = tid >> 5, lane = tid & 31, qr = lane >> 2, qc = lane & 3;
    float acc[4][4] = {};
    const uint32_t* zw = (const uint32_t*)&zb[0][0];
    const uint32_t* ww = (const uint32_t*)&wsm[0][0];
    #pragma unroll
    for (int kc = 0; kc < 4; kc++) {
        uint32_t af[4];
        int r = w * 16 + qr;
        af[0] = zw[r * 36 + kc * 8 + qc];
        af[1] = zw[(r + 8) * 36 + kc * 8 + qc];
        af[2] = zw[r * 36 + kc * 8 + 4 + qc];
        af[3] = zw[(r + 8) * 36 + kc * 8 + 4 + qc];
        #pragma unroll
        for (int j = 0; j < 4; j++) {
            int n = j * 8 + qr;
            mma_bf16(acc[j], af, ww[n * 36 + kc * 8 + qc], ww[n * 36 + kc * 8 + 4 + qc]);
        }
    }
    #pragma unroll
    for (int j = 0; j < 4; j++) {
        #pragma unroll
        for (int e = 0; e < 4; e++) {
            int mm = w * 16 + qr + ((e >= 2) ? 8 : 0);
            int n = j * 8 + 2 * qc + (e & 1);
            sOut[n][mm] = __float2bfloat16_rn(acc[j][e] + bsm[n]);
        }
    }
    __syncthreads();
    long long rg0 = (long long)blockIdx.x * 128;
    #pragma unroll
    for (int it = 0; it < 2; it++) {
        int lh = tid >> 3, part = (tid & 7) + it * 8;
        uint4 v = *(const uint4*)&sOut[lh][part * 8];
        __nv_bfloat16* dst = ((lh < 16) ? b0 : b1) +
                             (long long)(lh & 15) * S2_ + rg0 + part * 8;
        *(uint4*)dst = v;
    }
}

// ---------------------------------------------------------------------------
// Fused scores+softmax+Vt: per block = (head, 128 k-rows r) x all 1024 t.
// Pt[h][t][r] = exp(q[h,t]·k[h,r]/48 + bias)  (transposed, unnormalized)
// Vt[h][c][r] = v[h][r][c] / rowsum[r]        (transposed, scaled)
// Fragment loads via ldmatrix.
// ---------------------------------------------------------------------------
__global__ void __launch_bounds__(256) attn_sm_kernel(
    const __nv_bfloat16* __restrict__ kvg,
    const __nv_bfloat16* __restrict__ q,
    const __nv_bfloat16* __restrict__ bias,
    __nv_bfloat16* __restrict__ Pt,
    __nv_bfloat16* __restrict__ vt) {
    const int h = blockIdx.y;
    const int bm = blockIdx.x * 128;
    const int tid = threadIdx.x, lane = tid & 31, warp = tid >> 5;
    const int wm = warp >> 1, wn = warp & 1;
    const int qr = lane >> 2, qc = lane & 3;

    extern __shared__ char smraw[];
    __nv_bfloat16* Ks  = (__nv_bfloat16*)smraw;            // [128][56]
    __nv_bfloat16* Qs  = Ks + 128 * 56;                    // [2][64][56]
    __nv_bfloat16* Bsm = Qs + 2 * 64 * 56;                 // [2][128][72]
    __nv_bfloat16* sP  = Bsm + 2 * 128 * 72;               // [64][136]
    __shared__ float rs[128];

    const __nv_bfloat16* kbase = kvg + (long long)h * S_ * C3_;
    for (int id = tid; id < 128 * 24; id += 256) {
        int r = id / 24, c2 = id % 24;
        *(__nv_bfloat162*)&Ks[r * 56 + c2 * 2] =
            *(const __nv_bfloat162*)&kbase[(long long)(bm + r) * C3_ + c2 * 2];
    }
    if (tid < 128) rs[tid] = 0.f;

    const __nv_bfloat16* qbase = q + (long long)h * S_ * CH_;
    const __nv_bfloat16* bbase = bias + (long long)h * S2_;
    __nv_bfloat16* ptbase = Pt + (long long)h * S2_;
    uint32_t kSb = (uint32_t)__cvta_generic_to_shared(Ks);
    uint32_t qS = (uint32_t)__cvta_generic_to_shared(Qs);
    uint32_t bS = (uint32_t)__cvta_generic_to_shared(Bsm);

    auto issue = [&](int st, int tc) {
        // Q tile: 64 rows x 6 segs of 16B = FULL 48 elements per row
        #pragma unroll
        for (int i = 0; i < 2; i++) {
            int id = tid + i * 256;
            if (id < 384) {
                int t = id / 6, seg = id % 6;
                cp16(qS + st * 64 * 112 + t * 112 + seg * 16,
                     qbase + (long long)(tc * 64 + t) * CH_ + seg * 8, 16);
            }
        }
        // bias tile: 128 rows x 8 segs (64 cols, full)
        #pragma unroll
        for (int i = 0; i < 4; i++) {
            int id = tid + i * 256;
            int r = id >> 3, seg = id & 7;
            cp16(bS + st * 128 * 144 + r * 144 + seg * 16,
                 bbase + (long long)(bm + r) * S_ + tc * 64 + seg * 8, 16);
        }
    };

    // lane-dependent ldmatrix base offsets
    const uint32_t kA = kSb + (wm * 32 + (lane & 15)) * 112 + ((lane & 16) ? 16 : 0);
    const uint32_t qB0 = qS + (wn * 32 + (lane & 7)) * 112 + (((lane >> 3) & 1) ? 16 : 0);

    float rowacc[2][2] = {};
    issue(0, 0);
    CP_COMMIT();

    for (int tc = 0; tc < 16; tc++) {
        asm volatile("cp.async.wait_group 0;\n" ::);
        __syncthreads();
        if (tc + 1 < 16) issue((tc + 1) & 1, tc + 1);
        CP_COMMIT();
        int st = tc & 1;
        float acc[2][4][4] = {};
        #pragma unroll
        for (int ks = 0; ks < 3; ks++) {
            uint32_t af[2][4];
            ldsm_x4(af[0], kA + ks * 32);
            ldsm_x4(af[1], kA + ks * 32 + 16 * 112);
            #pragma unroll
            for (int j = 0; j < 4; j++) {
                uint32_t bf[2];
                ldsm_x2(bf, qB0 + st * 64 * 112 + j * 8 * 112 + ks * 32);
                mma_bf16(acc[0][j], af[0], bf[0], bf[1]);
                mma_bf16(acc[1][j], af[1], bf[0], bf[1]);
            }
        }
        #pragma unroll
        for (int i = 0; i < 2; i++) {
            #pragma unroll
            for (int eh = 0; eh < 2; eh++) {
                int ml = wm * 32 + i * 16 + qr + eh * 8;
                const __nv_bfloat16* brow = &Bsm[st * 128 * 72 + ml * 72];
                float part = 0.f;
                #pragma unroll
                for (int j = 0; j < 4; j++) {
                    int nl = wn * 32 + j * 8 + 2 * qc;
                    __nv_bfloat162 bb = *(const __nv_bfloat162*)&brow[nl];
                    float v0 = acc[i][j][eh * 2 + 0] * (1.f / 48.f) + toF(bb.x);
                    float v1 = acc[i][j][eh * 2 + 1] * (1.f / 48.f) + toF(bb.y);
                    float e0 = __expf(v0), e1 = __expf(v1);
                    sP[nl * 136 + ml]       = __float2bfloat16_rn(e0);
                    sP[(nl + 1) * 136 + ml] = __float2bfloat16_rn(e1);
                    part += e0 + e1;
                }
                rowacc[i][eh] += part;
            }
        }
        __syncthreads();
        #pragma unroll
        for (int it = 0; it < 4; it++) {
            int id = tid + it * 256;
            int trow = id >> 4, chunk = id & 15;
            uint4 v = *(const uint4*)&sP[trow * 136 + chunk * 8];
            *(uint4*)&ptbase[(long long)(tc * 64 + trow) * S_ + bm + chunk * 8] = v;
        }
    }
    #pragma unroll
    for (int i = 0; i < 2; i++) {
        #pragma unroll
        for (int eh = 0; eh < 2; eh++) {
            float v = rowacc[i][eh];
            v += __shfl_xor_sync(0xffffffffu, v, 1);
            v += __shfl_xor_sync(0xffffffffu, v, 2);
            if (qc == 0) atomicAdd(&rs[wm * 32 + i * 16 + qr + eh * 8], v);
        }
    }
    __syncthreads();

    // ---- fused Vt: scale V rows by 1/rowsum, transpose, store ----
    {
        __nv_bfloat16* sv = sP;   // reuse staging (48x136 <= 64x136)
        const __nv_bfloat16* vbase = kvg + (long long)h * S_ * C3_ + CH_;
        for (int id = tid; id < 128 * 24; id += 256) {
            int r = id / 24, c2 = id % 24;
            __nv_bfloat162 v = *(const __nv_bfloat162*)&vbase[(long long)(bm + r) * C3_ + 2 * c2];
            float sc = 1.0f / rs[r];
            sv[(2 * c2) * 136 + r]     = __float2bfloat16_rn(toF(v.x) * sc);
            sv[(2 * c2 + 1) * 136 + r] = __float2bfloat16_rn(toF(v.y) * sc);
        }
        __syncthreads();
        for (int id = tid; id < 48 * 16; id += 256) {
            int c = id >> 4, chunk = id & 15;
            *(uint4*)&vt[(long long)h * CH_ * S_ + (long long)c * S_ + bm + chunk * 8] =
                *(const uint4*)&sv[c * 136 + chunk * 8];
        }
    }
}

// ---------------------------------------------------------------------------
// Tensor-core bf16 GEMM (NT):  C[m,n] = sum_k A[m,k] * B[n,k]
// cp.async multi-stage ring, one sync per k-chunk, ldmatrix fragment loads.
// Block tile 128x64, BK=32, 256 threads (8 warps, 4x2), warp tile 32x32.
// ---------------------------------------------------------------------------
enum { EPI_PLAIN = 0, EPI_GSIG = 2, EPI_ADALN = 5, EPI_GLU = 6,
       EPI_SPLIT = 7, EPI_SGATE = 8, EPI_MULT = 9, EPI_TRF2 = 10 };

template <int EPI, bool DUAL, typename OutT, typename AuxT>
__global__ void __launch_bounds__(256) gemm_tc(
    const __nv_bfloat16* __restrict__ A, const __nv_bfloat16* __restrict__ B1,
    const __nv_bfloat16* __restrict__ B2, const float* __restrict__ bias,
    const AuxT* __restrict__ aux, const float* __restrict__ aux2,
    OutT* __restrict__ Cp, OutT* __restrict__ Cp2,
    int M, int N, int K, int lda, int ldb, int ldc, int ldc2, int nsplit, int aux_ld,
    long long sA, long long sB, long long sC, long long sAux) {
    constexpr int NST = DUAL ? 2 : 3;
    const int tid = threadIdx.x;
    const int lane = tid & 31, warp = tid >> 5;
    const int wm = warp >> 1, wn = warp & 1;
    const int bm = blockIdx.y * 128, bn = blockIdx.x * 64;
    const int bz = blockIdx.z;
    A += bz * sA;
    B1 += bz * sB;
    if constexpr (DUAL) B2 += bz * sB;
    Cp += bz * sC;
    if (aux) aux += bz * sAux;

    __shared__ __nv_bfloat16 As[NST][128][40];
    __shared__ __nv_bfloat16 Bs1[NST][64][40];
    __shared__ __nv_bfloat16 Bs2[DUAL ? NST : 1][64][40];

    float acc1[2][4][4] = {};
    float acc2[2][4][4] = {};
    const int qr = lane >> 2, qc = lane & 3;
    const int nk = (K + 31) / 32;

    uint32_t aBase = (uint32_t)__cvta_generic_to_shared(&As[0][0][0]);
    uint32_t bBase = (uint32_t)__cvta_generic_to_shared(&Bs1[0][0][0]);
    uint32_t b2Base = 0;
    if constexpr (DUAL) b2Base = (uint32_t)__cvta_generic_to_shared(&Bs2[0][0][0]);

    // lane-dependent ldmatrix base offsets (pitch 80 bytes)
    const uint32_t aLd  = aBase + (wm * 32 + (lane & 15)) * 80 + ((lane & 16) ? 16 : 0);
    const uint32_t bLd  = bBase + (wn * 32 + (lane & 7)) * 80 + (((lane >> 3) & 1) ? 16 : 0);
    uint32_t b2Ld = 0;
    if constexpr (DUAL) b2Ld = b2Base + (wn * 32 + (lane & 7)) * 80 + (((lane >> 3) & 1) ? 16 : 0);

    auto do_mma = [&](int st) {
        #pragma unroll
        for (int ks = 0; ks < 2; ks++) {
            uint32_t af[2][4];
            ldsm_x4(af[0], aLd + st * 128 * 80 + ks * 32);
            ldsm_x4(af[1], aLd + st * 128 * 80 + ks * 32 + 16 * 80);
            #pragma unroll
            for (int j = 0; j < 4; j++) {
                uint32_t bf[2];
                ldsm_x2(bf, bLd + st * 64 * 80 + j * 8 * 80 + ks * 32);
                mma_bf16(acc1[0][j], af[0], bf[0], bf[1]);
                mma_bf16(acc1[1][j], af[1], bf[0], bf[1]);
                if constexpr (DUAL) {
                    uint32_t bf2[2];
                    ldsm_x2(bf2, b2Ld + st * 64 * 80 + j * 8 * 80 + ks * 32);
                    mma_bf16(acc2[0][j], af[0], bf2[0], bf2[1]);
                    mma_bf16(acc2[1][j], af[1], bf2[0], bf2[1]);
                }
            }
        }
    };

    auto issue = [&](int st, int k0) {
        #pragma unroll
        for (int i = 0; i < 2; i++) {
            int id = tid + i * 256;
            int r = id >> 2, cp4 = id & 3;
            int kk = k0 + cp4 * 8;
            const __nv_bfloat16* src = A + (long long)(bm + r) * lda + kk;
            int sb = (kk < K) ? 16 : 0;
            if (!sb) src = A;
            cp16(aBase + st * 128 * 80 + r * 80 + cp4 * 16, src, sb);
        }
        {
            int r = tid >> 2, cp4 = tid & 3;
            int kk = k0 + cp4 * 8;
            int sb = (kk < K) ? 16 : 0;
            const __nv_bfloat16* src = B1 + (long long)(bn + r) * ldb + kk;
            if (!sb) src = B1;
            cp16(bBase + st * 64 * 80 + r * 80 + cp4 * 16, src, sb);
            if constexpr (DUAL) {
                const __nv_bfloat16* src2 = B2 + (long long)(bn + r) * ldb + kk;
                if (!sb) src2 = B2;
                cp16(b2Base + st * 64 * 80 + r * 80 + cp4 * 16, src2, sb);
            }
        }
    };

    #pragma unroll
    for (int p = 0; p < NST - 1; p++) {
        if (p < nk) issue(p, p * 32);
        CP_COMMIT();
    }
    for (int ic = 0; ic < nk; ic++) {
        if constexpr (NST == 3) asm volatile("cp.async.wait_group 1;\n" ::);
        else                    asm volatile("cp.async.wait_group 0;\n" ::);
        __syncthreads();
        int pn = ic + NST - 1;
        if (pn < nk) issue(pn % NST, pn * 32);
        CP_COMMIT();
        do_mma(ic % NST);
    }

    // ---- epilogue ----
    #pragma unroll
    for (int i = 0; i < 2; i++) {
        #pragma unroll
        for (int j = 0; j < 4; j++) {
            int m0 = bm + wm * 32 + i * 16 + qr;
            int n0 = bn + wn * 32 + j * 8 + 2 * qc;
            #pragma unroll
            for (int e = 0; e < 4; e++) {
                int m = m0 + ((e >= 2) ? 8 : 0);
                int n = n0 + (e & 1);
                if (n >= N) continue;
                float v = acc1[i][j][e];
                if constexpr (EPI == EPI_PLAIN) {
                    storeOut(v + (bias ? bias[n] : 0.f), &Cp[(long long)m * ldc + n]);
                } else if constexpr (EPI == EPI_GSIG) {
                    storeOut(sigf(toF(aux[(long long)m * aux_ld + n])) * v,
                             &Cp[(long long)m * ldc + n]);
                } else if constexpr (EPI == EPI_ADALN) {
                    int na = (n >= CA_) ? n - CA_ : n;
                    storeOut(sigf((v + bias[n]) * toF(aux[(long long)m * aux_ld + na]) +
                                  acc2[i][j][e]),
                             &Cp[(long long)m * ldc + n]);
                } else if constexpr (EPI == EPI_GLU) {
                    storeOut(v * sigf(v) * acc2[i][j][e], &Cp[(long long)m * ldc + n]);
                } else if constexpr (EPI == EPI_SPLIT) {
                    float out = v + ((n < nsplit) ? bias[n] : 0.f);
                    if (n < nsplit) storeOut(out, &Cp[(long long)m * ldc + n]);
                    else            storeOut(out, &Cp2[(long long)m * ldc2 + (n - nsplit)]);
                } else if constexpr (EPI == EPI_SGATE) {
                    bool sg = (((bn / 768) & 1) == 0);
                    float out = v + bias[n];
                    storeOut(sg ? sigf(out) : out, &Cp[(long long)m * ldc + n]);
                } else if constexpr (EPI == EPI_MULT) {
                    storeOut(toF(aux[(long long)m * aux_ld + n]) * v,
                             &Cp[(long long)m * ldc + n]);
                } else {  // EPI_TRF2
                    storeOut(aux2[(long long)m * CA_ + n] +
                             sigf(toF(aux[(long long)m * aux_ld + n]) * v),
                             &Cp[(long long)m * ldc + n]);
                }
            }
        }
    }
}

// ---------------------------------------------------------------------------
// Host orchestration
// ---------------------------------------------------------------------------
extern "C" void kernel_launch(void* const* d_in, const int* in_sizes, int n_in,
                              void* d_out, int out_size) {
    const float* A0        = (const float*)d_in[0];
    const float* Sm        = (const float*)d_in[1];
    const float* Z         = (const float*)d_in[2];
    const float* attn_sn_w = (const float*)d_in[3];
    const float* attn_pb_w = (const float*)d_in[4];
    const float* attn_pb_b = (const float*)d_in[5];
    const float* attn_pnb_w= (const float*)d_in[6];
    const float* pair_w    = (const float*)d_in[7];
    const float* pair_b    = (const float*)d_in[8];
    const float* q_w       = (const float*)d_in[9];
    const float* q_b       = (const float*)d_in[10];
    const float* kvg_w     = (const float*)d_in[11];
    const float* bias_w    = (const float*)d_in[12];
    const float* bias_b    = (const float*)d_in[13];
    const float* ao_w      = (const float*)d_in[14];
    const float* out_w     = (const float*)d_in[15];
    const float* out_b     = (const float*)d_in[16];
    const float* tr_sn_w   = (const float*)d_in[17];
    const float* tr_pb_w   = (const float*)d_in[18];
    const float* tr_pb_b   = (const float*)d_in[19];
    const float* tr_pnb_w  = (const float*)d_in[20];
    const float* tr_a_w    = (const float*)d_in[21];
    const float* tr_s_w    = (const float*)d_in[22];
    const float* tr_s_b    = (const float*)d_in[23];
    const float* tr_b_w    = (const float*)d_in[24];
    float* OUT = (float*)d_out;

    float *an, *aout, *anew, *wbias, *sg, *adab, *sgb;
    __nv_bfloat16 *bb0, *bb1, *wbf, *shatb, *a23b, *qb, *kvgb, *obb, *bbb, *pbf, *vtb, *wpbf;
    cudaGetSymbolAddress((void**)&an, g_an);
    cudaGetSymbolAddress((void**)&aout, g_aout);
    cudaGetSymbolAddress((void**)&anew, g_anew);
    cudaGetSymbolAddress((void**)&wbias, g_wbias);
    cudaGetSymbolAddress((void**)&sg, g_sg);
    cudaGetSymbolAddress((void**)&adab, g_adab);
    cudaGetSymbolAddress((void**)&sgb, g_sgb);
    cudaGetSymbolAddress((void**)&bb0, g_bb0);
    cudaGetSymbolAddress((void**)&bb1, g_bb1);
    cudaGetSymbolAddress((void**)&wbf, g_wbf);
    cudaGetSymbolAddress((void**)&shatb, g_shatb);
    cudaGetSymbolAddress((void**)&a23b, g_a23b);
    cudaGetSymbolAddress((void**)&qb, g_qb);
    cudaGetSymbolAddress((void**)&kvgb, g_kvgb);
    cudaGetSymbolAddress((void**)&obb, g_obb);
    cudaGetSymbolAddress((void**)&bbb, g_bbb);
    cudaGetSymbolAddress((void**)&pbf, g_pbf);
    cudaGetSymbolAddress((void**)&vtb, g_vtb);
    cudaGetSymbolAddress((void**)&wpbf, g_wpbf);

    cudaFuncSetAttribute(attn_sm_kernel, cudaFuncAttributeMaxDynamicSharedMemorySize, 82944);

    // ---- conversion table ----
    CvtArgs ca;
    long long off = 0;
    int ns = 0;
    long long wo_ada1[2], wo_ada2[2], wo_q[2], wo_ao[2], wo_tra[2], wo_trb[2], wo_sg, wo_s;
    auto seg = [&](const float* s, int len, const float* sc) -> long long {
        ca.src[ns] = s; ca.scl[ns] = sc; ca.dst[ns] = wbf + off; ca.len[ns] = len;
        long long o = off; off += len; ns++; return o;
    };
    for (int l = 0; l < 2; l++) {
        wo_ada1[l] = seg(attn_pb_w  + (long long)l * CA_ * CS_, CA_ * CS_, attn_sn_w + l * CS_);
                     seg(tr_pb_w   + (long long)l * CA_ * CS_, CA_ * CS_, tr_sn_w + l * CS_);
        wo_ada2[l] = seg(attn_pnb_w + (long long)l * CA_ * CS_, CA_ * CS_, attn_sn_w + l * CS_);
                     seg(tr_pnb_w  + (long long)l * CA_ * CS_, CA_ * CS_, tr_sn_w + l * CS_);
        wo_q[l]    = seg(q_w   + (long long)l * CA_ * CA_, CA_ * CA_, nullptr);
                     seg(kvg_w + (long long)l * 3 * CA_ * CA_, 3 * CA_ * CA_, nullptr);
        wo_ao[l]   = seg(ao_w  + (long long)l * CA_ * CA_, CA_ * CA_, nullptr);
        wo_tra[l]  = seg(tr_a_w + (long long)l * 4 * CA_ * CA_, 4 * CA_ * CA_, nullptr);
        wo_trb[l]  = seg(tr_b_w + (long long)l * 2 * CA_ * CA_, 2 * CA_ * CA_, nullptr);
    }
    wo_sg = seg(out_w, CA_ * CS_, nullptr);
            seg(tr_s_w, CA_ * CS_, nullptr);
            seg(out_w + (long long)CA_ * CS_, CA_ * CS_, nullptr);
            seg(tr_s_w + (long long)CA_ * CS_, CA_ * CS_, nullptr);
    wo_s = seg(Sm, S_ * CS_, nullptr);
    ca.smod = CS_;
    ca.nseg = ns;

    cvt_kernel<<<dim3(128, ns), 256>>>(ca);
    bias_prep<<<25, 256>>>(attn_pb_b, tr_pb_b, out_b, tr_s_b, adab, sgb,
                           pair_w, pair_b, bias_w, bias_b, wpbf, wbias);
    ln_kernel<__nv_bfloat16><<<S_ / 8, 256>>>(Sm, shatb, CS_);
    zproj_kernel<<<(S_ * S_) / 128, 256>>>(Z, wpbf, wbias, bb0, bb1);

    const __nv_bfloat16* s_bf = wbf + wo_s;

    // sgate: [og l0 | tg l0 | og l1 | tg l1]  (layer-independent)
    gemm_tc<EPI_SGATE, false, float, float><<<dim3(48, 8, 1), 256>>>(
        s_bf, wbf + wo_sg, nullptr, sgb, nullptr, nullptr, sg, nullptr,
        S_, 3072, CS_, CS_, CS_, 3072, 0, 0, 0, 0, 0, 0, 0);

    for (int l = 0; l < 2; l++) {
        const float* ain = l ? anew : A0;
        float* aoutp = l ? OUT : anew;
        const __nv_bfloat16* bbl = l ? bb1 : bb0;

        ln_kernel<float><<<S_ / 8, 256>>>(ain, an, CA_);

        // combined adaLN: a2|a3 = sigmoid((pb·sn+b)*an + pnb·sn), N=1536
        gemm_tc<EPI_ADALN, true, __nv_bfloat16, float><<<dim3(24, 8, 1), 256>>>(
            shatb, wbf + wo_ada1[l], wbf + wo_ada2[l], adab + (long long)l * 1536,
            an, nullptr, a23b, nullptr,
            S_, 1536, CS_, CS_, CS_, 1536, 0, 0, CA_, 0, 0, 0, 0);

        // combined q+kvg: N=3072, split epilogue -> qb / kvgb
        gemm_tc<EPI_SPLIT, false, __nv_bfloat16, float><<<dim3(48, 8, 1), 256>>>(
            a23b, wbf + wo_q[l], nullptr, q_b + (long long)l * CA_,
            nullptr, nullptr, qb, kvgb,
            S_, 3072, CA_, 1536, CA_, CA_, 3 * CA_, CA_, 0, 0, 0, 0, 0);

        // fused scores + softmax + Vt
        attn_sm_kernel<<<dim3(8, 16), 256, 82944>>>(kvgb, qb, bbl, pbf, vtb);

        // o[t,c] = sum_r Pt[t,r]*Vt[c,r];  fused sigmoid(g)*o
        gemm_tc<EPI_GSIG, false, __nv_bfloat16, __nv_bfloat16><<<dim3(1, 8, 16), 256>>>(
            pbf, vtb, nullptr, nullptr, kvgb + 2 * CH_, nullptr, obb, nullptr,
            S_, CH_, S_, S_, S_, CH_, 0, 0, C3_,
            (long long)S2_, (long long)CH_ * S_, (long long)S_ * CH_,
            (long long)S_ * C3_);

        // aout = og * ((sig(g)*o) @ ao_w^T)
        gemm_tc<EPI_MULT, false, float, float><<<dim3(12, 8, 1), 256>>>(
            obb, wbf + wo_ao[l], nullptr, nullptr, sg + (long long)l * 1536, nullptr,
            aout, nullptr,
            S_, CA_, CA_, CA_, CA_, CA_, 0, 0, 3072, 0, 0, 0, 0);

        // bb = silu(a3 @ W1^T) * (a3 @ W2^T)
        gemm_tc<EPI_GLU, true, __nv_bfloat16, float><<<dim3(24, 8, 1), 256>>>(
            a23b + CA_, wbf + wo_tra[l], wbf + wo_tra[l] + (long long)2 * CA_ * CA_, nullptr,
            nullptr, nullptr, bbb, nullptr,
            S_, 2 * CA_, CA_, 1536, CA_, 2 * CA_, 0, 0, 0, 0, 0, 0, 0);

        // a_next = aout + sigmoid(tg * (bb @ tr_b_w^T))
        gemm_tc<EPI_TRF2, false, float, float><<<dim3(12, 8, 1), 256>>>(
            bbb, wbf + wo_trb[l], nullptr, nullptr,
            sg + (long long)l * 1536 + CA_, aout, aoutp, nullptr,
            S_, CA_, 2 * CA_, 2 * CA_, 2 * CA_, CA_, 0, 0, 3072, 0, 0, 0, 0);
    }
}